// round 3
// baseline (speedup 1.0000x reference)
#include <cuda_runtime.h>
#include <math.h>

// ---------------------------------------------------------------------------
// TransformerBlock: x(2,2048,1024) fp32
//   LN1 -> Q,K,V proj -> 16-head attention (D=64) -> Wo + residual
//   -> LN2 -> FFN (GELU exact) + residual
// Round-2 baseline: full fp32 (guaranteed accuracy), tiled SIMT GEMMs +
// flash-style attention. Scratch lives in __device__ globals (no allocs).
// ---------------------------------------------------------------------------

#define MTOT   4096   // B*N rows
#define CDIM   1024
#define HIDDIM 4096
#define NBATCH 2
#define SEQLEN 2048
#define NHEADS 16
#define HDIM   64

__device__ float g_h [MTOT * CDIM];            // LN output (reused for LN1/LN2)
__device__ float g_q [MTOT * CDIM];
__device__ float g_k [MTOT * CDIM];
__device__ float g_v [MTOT * CDIM];
__device__ float g_o [MTOT * CDIM];            // attention output
__device__ float g_x1[MTOT * CDIM];            // x + attn residual
__device__ float g_ff[(size_t)MTOT * HIDDIM];  // FFN hidden

// ---------------------------------------------------------------------------
// LayerNorm: one block per row (C=1024), 256 threads, float4 per thread.
// ---------------------------------------------------------------------------
__global__ __launch_bounds__(256) void ln_kernel(
    const float* __restrict__ in, const float* __restrict__ gamma,
    const float* __restrict__ beta, float* __restrict__ out)
{
    const int row = blockIdx.x;
    const int t   = threadIdx.x;
    const float4 v = ((const float4*)(in + (size_t)row * CDIM))[t];

    float s  = v.x + v.y + v.z + v.w;
    float ss = v.x * v.x + v.y * v.y + v.z * v.z + v.w * v.w;
    #pragma unroll
    for (int o = 16; o > 0; o >>= 1) {
        s  += __shfl_xor_sync(0xffffffffu, s,  o);
        ss += __shfl_xor_sync(0xffffffffu, ss, o);
    }

    __shared__ float sh_s[8], sh_ss[8], sh_stat[2];
    const int w = t >> 5, lane = t & 31;
    if (lane == 0) { sh_s[w] = s; sh_ss[w] = ss; }
    __syncthreads();
    if (t == 0) {
        float ts = 0.f, tss = 0.f;
        #pragma unroll
        for (int i = 0; i < 8; i++) { ts += sh_s[i]; tss += sh_ss[i]; }
        const float mu  = ts * (1.0f / CDIM);
        const float var = tss * (1.0f / CDIM) - mu * mu;
        sh_stat[0] = mu;
        sh_stat[1] = rsqrtf(var + 1e-5f);
    }
    __syncthreads();
    const float mu = sh_stat[0], r = sh_stat[1];

    const float4 g4 = ((const float4*)gamma)[t];
    const float4 b4 = ((const float4*)beta)[t];
    float4 o;
    o.x = (v.x - mu) * r * g4.x + b4.x;
    o.y = (v.y - mu) * r * g4.y + b4.y;
    o.z = (v.z - mu) * r * g4.z + b4.z;
    o.w = (v.w - mu) * r * g4.w + b4.w;
    ((float4*)(out + (size_t)row * CDIM))[t] = o;
}

// ---------------------------------------------------------------------------
// fp32 GEMM: out[M,N] = A[M,K] @ W[K,N] + bias  (+residual / +GELU)
// 128x128 block tile, BK=8, 256 threads, 8x8 per thread.
// EPI: 0 = bias, 1 = bias + residual, 2 = bias + exact GELU
// ---------------------------------------------------------------------------
__device__ __forceinline__ float gelu_exact(float x) {
    return 0.5f * x * (1.0f + erff(x * 0.70710678118654752f));
}

template <int EPI>
__global__ __launch_bounds__(256) void gemm_kernel(
    const float* __restrict__ A, const float* __restrict__ W,
    const float* __restrict__ bias, const float* __restrict__ res,
    float* __restrict__ Cout, int M, int K, int N)
{
    __shared__ float As[8][128];   // [k][m] (transposed)
    __shared__ float Bs[8][128];   // [k][n]

    const int bm  = blockIdx.y * 128;
    const int bn  = blockIdx.x * 128;
    const int tid = threadIdx.x;
    const int tx  = tid & 15;      // 16 cols of 8
    const int ty  = tid >> 4;      // 16 rows of 8

    // global-load mapping
    const int arow = tid >> 1;           // 0..127
    const int acol = (tid & 1) << 2;     // 0 or 4
    const int brow = tid >> 5;           // 0..7
    const int bcol = (tid & 31) << 2;    // 0..124

    const float* Aptr = A + (size_t)(bm + arow) * K + acol;
    const float* Wptr = W + (size_t)brow * N + bn + bcol;

    float acc[8][8] = {};

    for (int k0 = 0; k0 < K; k0 += 8) {
        const float4 a = *(const float4*)(Aptr + k0);
        As[acol + 0][arow] = a.x;
        As[acol + 1][arow] = a.y;
        As[acol + 2][arow] = a.z;
        As[acol + 3][arow] = a.w;
        const float4 b = *(const float4*)(Wptr + (size_t)k0 * N);
        *(float4*)&Bs[brow][bcol] = b;
        __syncthreads();

        #pragma unroll
        for (int kk = 0; kk < 8; kk++) {
            float af[8], bf[8];
            *(float4*)&af[0] = *(const float4*)&As[kk][ty * 8];
            *(float4*)&af[4] = *(const float4*)&As[kk][ty * 8 + 4];
            *(float4*)&bf[0] = *(const float4*)&Bs[kk][tx * 8];
            *(float4*)&bf[4] = *(const float4*)&Bs[kk][tx * 8 + 4];
            #pragma unroll
            for (int i = 0; i < 8; i++)
                #pragma unroll
                for (int j = 0; j < 8; j++)
                    acc[i][j] = fmaf(af[i], bf[j], acc[i][j]);
        }
        __syncthreads();
    }

    const int om = bm + ty * 8;
    const int on = bn + tx * 8;
    float4 bias4[2];
    bias4[0] = *(const float4*)(bias + on);
    bias4[1] = *(const float4*)(bias + on + 4);

    #pragma unroll
    for (int i = 0; i < 8; i++) {
        const size_t rbase = (size_t)(om + i) * N + on;
        #pragma unroll
        for (int jv = 0; jv < 2; jv++) {
            float4 t;
            t.x = acc[i][jv * 4 + 0] + bias4[jv].x;
            t.y = acc[i][jv * 4 + 1] + bias4[jv].y;
            t.z = acc[i][jv * 4 + 2] + bias4[jv].z;
            t.w = acc[i][jv * 4 + 3] + bias4[jv].w;
            if (EPI == 1) {
                const float4 rr = *(const float4*)(res + rbase + jv * 4);
                t.x += rr.x; t.y += rr.y; t.z += rr.z; t.w += rr.w;
            }
            if (EPI == 2) {
                t.x = gelu_exact(t.x); t.y = gelu_exact(t.y);
                t.z = gelu_exact(t.z); t.w = gelu_exact(t.w);
            }
            *(float4*)(Cout + rbase + jv * 4) = t;
        }
    }
}

// ---------------------------------------------------------------------------
// Flash-style attention. Grid: (SEQ/64, NHEADS, NBATCH), 256 threads.
// BQ=64 queries, BKV=32 keys per tile, D=64. All fp32, online softmax.
// Q/K/V layout: [b*SEQ + n][h*HDIM + d] (row stride CDIM).
// ---------------------------------------------------------------------------
__global__ __launch_bounds__(256) void attn_kernel(
    const float* __restrict__ Q, const float* __restrict__ K,
    const float* __restrict__ V, float* __restrict__ O)
{
    constexpr int BQ = 64, BK = 32, D = HDIM;
    __shared__ float Qs[D][BQ];       // [d][i], pre-scaled
    __shared__ float Ks[D][BK];       // [d][j]
    __shared__ float Vs[BK][D];       // [j][d]
    __shared__ float Ps[BQ][BK + 1];  // exp(S - m), padded

    const int qt = blockIdx.x;
    const int h  = blockIdx.y;
    const int b  = blockIdx.z;
    const int tid = threadIdx.x;
    const int tx = tid & 15;          // 16 groups over cols
    const int ty = tid >> 4;          // 16 groups over rows

    const float scale = 0.125f;       // 1/sqrt(64)
    const size_t head_off = (size_t)h * HDIM;

    // load Q tile (64x64), transposed + pre-scaled: 1024 float4 / 256 thr
    #pragma unroll
    for (int it = 0; it < 4; it++) {
        const int idx = it * 256 + tid;
        const int r = idx >> 4;                // 0..63
        const int c = (idx & 15) << 2;         // 0..60
        const float4 qv = *(const float4*)(
            Q + (size_t)(b * SEQLEN + qt * BQ + r) * CDIM + head_off + c);
        Qs[c + 0][r] = qv.x * scale;
        Qs[c + 1][r] = qv.y * scale;
        Qs[c + 2][r] = qv.z * scale;
        Qs[c + 3][r] = qv.w * scale;
    }

    float m_run[4], l_run[4], o_acc[4][4];
    #pragma unroll
    for (int i = 0; i < 4; i++) {
        m_run[i] = -1e30f; l_run[i] = 0.f;
        #pragma unroll
        for (int d = 0; d < 4; d++) o_acc[i][d] = 0.f;
    }
    __syncthreads();

    for (int kt = 0; kt < SEQLEN / BK; kt++) {
        // load K (transposed) and V (row-major): 512 float4 each
        #pragma unroll
        for (int it = 0; it < 2; it++) {
            const int idx = it * 256 + tid;
            const int r = idx >> 4;            // 0..31
            const int c = (idx & 15) << 2;     // 0..60
            const size_t gidx =
                (size_t)(b * SEQLEN + kt * BK + r) * CDIM + head_off + c;
            const float4 kv = *(const float4*)(K + gidx);
            Ks[c + 0][r] = kv.x; Ks[c + 1][r] = kv.y;
            Ks[c + 2][r] = kv.z; Ks[c + 3][r] = kv.w;
            *(float4*)&Vs[r][c] = *(const float4*)(V + gidx);
        }
        __syncthreads();

        // S = Qs^T @ Ks : per-thread 4 rows x 2 cols
        float s[4][2] = {};
        #pragma unroll 8
        for (int d = 0; d < D; d++) {
            const float4 a = *(const float4*)&Qs[d][ty * 4];
            const float b0 = Ks[d][tx * 2 + 0];
            const float b1 = Ks[d][tx * 2 + 1];
            s[0][0] = fmaf(a.x, b0, s[0][0]); s[0][1] = fmaf(a.x, b1, s[0][1]);
            s[1][0] = fmaf(a.y, b0, s[1][0]); s[1][1] = fmaf(a.y, b1, s[1][1]);
            s[2][0] = fmaf(a.z, b0, s[2][0]); s[2][1] = fmaf(a.z, b1, s[2][1]);
            s[3][0] = fmaf(a.w, b0, s[3][0]); s[3][1] = fmaf(a.w, b1, s[3][1]);
        }

        // online softmax: reduce across the 16 tx lanes (xor 8,4,2,1 stays
        // within each 16-lane half-warp since groups are 16-aligned)
        #pragma unroll
        for (int i = 0; i < 4; i++) {
            float mx = fmaxf(s[i][0], s[i][1]);
            #pragma unroll
            for (int off = 8; off > 0; off >>= 1)
                mx = fmaxf(mx, __shfl_xor_sync(0xffffffffu, mx, off));
            const float mnew = fmaxf(m_run[i], mx);
            const float corr = __expf(m_run[i] - mnew);
            const float e0 = __expf(s[i][0] - mnew);
            const float e1 = __expf(s[i][1] - mnew);
            float sum = e0 + e1;
            #pragma unroll
            for (int off = 8; off > 0; off >>= 1)
                sum += __shfl_xor_sync(0xffffffffu, sum, off);
            l_run[i] = l_run[i] * corr + sum;
            m_run[i] = mnew;
            #pragma unroll
            for (int d = 0; d < 4; d++) o_acc[i][d] *= corr;
            Ps[ty * 4 + i][tx * 2 + 0] = e0;
            Ps[ty * 4 + i][tx * 2 + 1] = e1;
        }
        __syncthreads();

        // O += P @ V : per-thread 4 rows x 4 d-cols
        #pragma unroll 8
        for (int j = 0; j < BK; j++) {
            const float4 vv = *(const float4*)&Vs[j][tx * 4];
            #pragma unroll
            for (int i = 0; i < 4; i++) {
                const float p = Ps[ty * 4 + i][j];
                o_acc[i][0] = fmaf(p, vv.x, o_acc[i][0]);
                o_acc[i][1] = fmaf(p, vv.y, o_acc[i][1]);
                o_acc[i][2] = fmaf(p, vv.z, o_acc[i][2]);
                o_acc[i][3] = fmaf(p, vv.w, o_acc[i][3]);
            }
        }
        __syncthreads();
    }

    // normalize + write back
    #pragma unroll
    for (int i = 0; i < 4; i++) {
        const float inv = 1.0f / l_run[i];
        float4 ov;
        ov.x = o_acc[i][0] * inv; ov.y = o_acc[i][1] * inv;
        ov.z = o_acc[i][2] * inv; ov.w = o_acc[i][3] * inv;
        *(float4*)(O + (size_t)(b * SEQLEN + qt * BQ + ty * 4 + i) * CDIM +
                   head_off + tx * 4) = ov;
    }
}

// ---------------------------------------------------------------------------
// kernel_launch
// ---------------------------------------------------------------------------
extern "C" void kernel_launch(void* const* d_in, const int* in_sizes, int n_in,
                              void* d_out, int out_size)
{
    const float* x   = (const float*)d_in[0];
    const float* g1  = (const float*)d_in[1];
    const float* b1  = (const float*)d_in[2];
    const float* Wq  = (const float*)d_in[3];
    const float* bq  = (const float*)d_in[4];
    const float* Wk  = (const float*)d_in[5];
    const float* bk  = (const float*)d_in[6];
    const float* Wv  = (const float*)d_in[7];
    const float* bv  = (const float*)d_in[8];
    const float* Wo  = (const float*)d_in[9];
    const float* bo  = (const float*)d_in[10];
    const float* g2  = (const float*)d_in[11];
    const float* b2  = (const float*)d_in[12];
    const float* W1  = (const float*)d_in[13];
    const float* bf1 = (const float*)d_in[14];
    const float* W2  = (const float*)d_in[15];
    const float* bf2 = (const float*)d_in[16];
    float* out = (float*)d_out;

    float *ph, *pq, *pk, *pv, *po, *px1, *pff;
    cudaGetSymbolAddress((void**)&ph,  g_h);
    cudaGetSymbolAddress((void**)&pq,  g_q);
    cudaGetSymbolAddress((void**)&pk,  g_k);
    cudaGetSymbolAddress((void**)&pv,  g_v);
    cudaGetSymbolAddress((void**)&po,  g_o);
    cudaGetSymbolAddress((void**)&px1, g_x1);
    cudaGetSymbolAddress((void**)&pff, g_ff);

    const dim3 gC(CDIM / 128, MTOT / 128);     // (8, 32)
    const dim3 gH(HIDDIM / 128, MTOT / 128);   // (32, 32)

    // LN1
    ln_kernel<<<MTOT, 256>>>(x, g1, b1, ph);
    // Q, K, V projections
    gemm_kernel<0><<<gC, 256>>>(ph, Wq, bq, nullptr, pq, MTOT, CDIM, CDIM);
    gemm_kernel<0><<<gC, 256>>>(ph, Wk, bk, nullptr, pk, MTOT, CDIM, CDIM);
    gemm_kernel<0><<<gC, 256>>>(ph, Wv, bv, nullptr, pv, MTOT, CDIM, CDIM);
    // attention
    attn_kernel<<<dim3(SEQLEN / 64, NHEADS, NBATCH), 256>>>(pq, pk, pv, po);
    // output projection + residual
    gemm_kernel<1><<<gC, 256>>>(po, Wo, bo, x, px1, MTOT, CDIM, CDIM);
    // LN2
    ln_kernel<<<MTOT, 256>>>(px1, g2, b2, ph);
    // FFN
    gemm_kernel<2><<<gH, 256>>>(ph, W1, bf1, nullptr, pff, MTOT, CDIM, HIDDIM);
    gemm_kernel<1><<<gC, 256>>>(pff, W2, bf2, px1, out, MTOT, HIDDIM, CDIM);
}

// round 5
// speedup vs baseline: 1.7068x; 1.7068x over previous
#include <cuda_runtime.h>
#include <cuda_bf16.h>
#include <math.h>
#include <stdint.h>

// ---------------------------------------------------------------------------
// TransformerBlock on GB300 (sm_103a, but harness compiles PTX as compute_103
// => NO 'a'-gated features: no tcgen05 / TMA-tensor / elect.sync).
// Round 5: GEMMs via portable mma.sync bf16 (m16n8k16) with split hi+lo
// (3 MMAs per K-step) for fp32-grade accuracy. cp.async 2-stage pipeline.
// Attention stays fp32 SIMT (proven), emits bf16 hi/lo for the Wo GEMM.
// ---------------------------------------------------------------------------

#define MTOT   4096
#define CDIM   1024
#define HIDDIM 4096
#define NBATCH 2
#define SEQLEN 2048
#define NHEADS 16
#define HDIM   64

// ------------------------------ scratch ------------------------------------
__device__ float g_q [MTOT * CDIM];
__device__ float g_k [MTOT * CDIM];
__device__ float g_v [MTOT * CDIM];
__device__ float g_x1[MTOT * CDIM];
__device__ __nv_bfloat16 g_hh[MTOT * CDIM], g_hl[MTOT * CDIM];   // LN out
__device__ __nv_bfloat16 g_oh[MTOT * CDIM], g_ol[MTOT * CDIM];   // attn out
__device__ __nv_bfloat16 g_fh[(size_t)MTOT * HIDDIM];            // FFN hidden
__device__ __nv_bfloat16 g_fl[(size_t)MTOT * HIDDIM];
__device__ __nv_bfloat16 g_wh[(size_t)HIDDIM * CDIM];            // W^T scratch
__device__ __nv_bfloat16 g_wl[(size_t)HIDDIM * CDIM];

// --------------------------- helpers ---------------------------------------
__device__ __forceinline__ uint32_t smem_u32(const void* p) {
    uint32_t a;
    asm("{ .reg .u64 t; cvta.to.shared.u64 t, %1; cvt.u32.u64 %0, t; }"
        : "=r"(a) : "l"(p));
    return a;
}
__device__ __forceinline__ void cpasync16(uint32_t saddr, const void* g) {
    asm volatile("cp.async.cg.shared.global [%0], [%1], 16;"
                 :: "r"(saddr), "l"(g));
}
#define CP_COMMIT() asm volatile("cp.async.commit_group;" ::: "memory")
#define CP_WAIT(n)  asm volatile("cp.async.wait_group %0;" :: "n"(n) : "memory")

__device__ __forceinline__ void ldmA(uint32_t* a, uint32_t addr) {
    asm volatile("ldmatrix.sync.aligned.m8n8.x4.shared.b16 {%0,%1,%2,%3}, [%4];"
        : "=r"(a[0]), "=r"(a[1]), "=r"(a[2]), "=r"(a[3]) : "r"(addr));
}
__device__ __forceinline__ void ldmB(uint32_t* b, uint32_t addr) {
    asm volatile("ldmatrix.sync.aligned.m8n8.x2.shared.b16 {%0,%1}, [%2];"
        : "=r"(b[0]), "=r"(b[1]) : "r"(addr));
}
__device__ __forceinline__ void mma16816(float* d, const uint32_t* a,
                                         const uint32_t* b) {
    asm volatile(
        "mma.sync.aligned.m16n8k16.row.col.f32.bf16.bf16.f32 "
        "{%0,%1,%2,%3}, {%4,%5,%6,%7}, {%8,%9}, {%0,%1,%2,%3};"
        : "+f"(d[0]), "+f"(d[1]), "+f"(d[2]), "+f"(d[3])
        : "r"(a[0]), "r"(a[1]), "r"(a[2]), "r"(a[3]), "r"(b[0]), "r"(b[1]));
}

__device__ __forceinline__ void split_bf16(float v, __nv_bfloat16& h,
                                           __nv_bfloat16& l) {
    h = __float2bfloat16(v);
    l = __float2bfloat16(v - __bfloat162float(h));
}
__device__ __forceinline__ float gelu_exact(float x) {
    return 0.5f * x * (1.0f + erff(x * 0.70710678118654752f));
}

// ---------------------------------------------------------------------------
// LayerNorm -> bf16 hi/lo split. One block per row, 256 thr.
// ---------------------------------------------------------------------------
__global__ __launch_bounds__(256) void ln_kernel(
    const float* __restrict__ in, const float* __restrict__ gamma,
    const float* __restrict__ beta,
    __nv_bfloat16* __restrict__ oh, __nv_bfloat16* __restrict__ ol)
{
    const int row = blockIdx.x;
    const int t   = threadIdx.x;
    const float4 v = ((const float4*)(in + (size_t)row * CDIM))[t];

    float s  = v.x + v.y + v.z + v.w;
    float ss = v.x * v.x + v.y * v.y + v.z * v.z + v.w * v.w;
    #pragma unroll
    for (int o = 16; o > 0; o >>= 1) {
        s  += __shfl_xor_sync(0xffffffffu, s,  o);
        ss += __shfl_xor_sync(0xffffffffu, ss, o);
    }
    __shared__ float sh_s[8], sh_ss[8], sh_stat[2];
    const int w = t >> 5, lane = t & 31;
    if (lane == 0) { sh_s[w] = s; sh_ss[w] = ss; }
    __syncthreads();
    if (t == 0) {
        float ts = 0.f, tss = 0.f;
        #pragma unroll
        for (int i = 0; i < 8; i++) { ts += sh_s[i]; tss += sh_ss[i]; }
        const float mu  = ts * (1.0f / CDIM);
        const float var = tss * (1.0f / CDIM) - mu * mu;
        sh_stat[0] = mu; sh_stat[1] = rsqrtf(var + 1e-5f);
    }
    __syncthreads();
    const float mu = sh_stat[0], r = sh_stat[1];

    const float4 g4 = ((const float4*)gamma)[t];
    const float4 b4 = ((const float4*)beta)[t];
    float y[4];
    y[0] = (v.x - mu) * r * g4.x + b4.x;
    y[1] = (v.y - mu) * r * g4.y + b4.y;
    y[2] = (v.z - mu) * r * g4.z + b4.z;
    y[3] = (v.w - mu) * r * g4.w + b4.w;

    __align__(8) __nv_bfloat16 hh[4], ll[4];
    #pragma unroll
    for (int i = 0; i < 4; i++) split_bf16(y[i], hh[i], ll[i]);
    *(uint2*)(oh + (size_t)row * CDIM + t * 4) = *(uint2*)hh;
    *(uint2*)(ol + (size_t)row * CDIM + t * 4) = *(uint2*)ll;
}

// ---------------------------------------------------------------------------
// Weight transpose + bf16 split:  W[K,N] fp32 -> Th/Tl[N,K] bf16
// ---------------------------------------------------------------------------
__global__ __launch_bounds__(256) void wtrans_kernel(
    const float* __restrict__ W, __nv_bfloat16* __restrict__ Th,
    __nv_bfloat16* __restrict__ Tl, int K, int N)
{
    __shared__ float t[32][33];
    const int n0 = blockIdx.x * 32, k0 = blockIdx.y * 32;
    const int tx = threadIdx.x & 31, ty = threadIdx.x >> 5;
    #pragma unroll
    for (int i = ty; i < 32; i += 8)
        t[i][tx] = W[(size_t)(k0 + i) * N + n0 + tx];
    __syncthreads();
    #pragma unroll
    for (int i = ty; i < 32; i += 8) {
        const float v = t[tx][i];
        __nv_bfloat16 h, l;
        split_bf16(v, h, l);
        Th[(size_t)(n0 + i) * K + k0 + tx] = h;
        Tl[(size_t)(n0 + i) * K + k0 + tx] = l;
    }
}

// ---------------------------------------------------------------------------
// mma.sync GEMM:  out[M,N] = (Ah+Al)[M,K] @ (Bh+Bl)[N,K]^T  (split 3-MMA)
// CTA 128x128, 8 warps (2x4, each 64x32), K-chunk 64, 2-stage cp.async.
// Smem tile: 128 rows x 64 bf16, padded row stride 144B (conflict-free).
// EPI: 0 bias->fp32, 1 bias+res->fp32, 2 bias+GELU->bf16 hi/lo
// ---------------------------------------------------------------------------
#define TSTRIDE 144                     // bytes per padded row
#define TILE_B  (128 * TSTRIDE)         // 18432 B per tile
#define STAGE_B (4 * TILE_B)            // Ah,Al,Bh,Bl per stage
#define GSMEM   (2 * STAGE_B)           // 147456 B

__device__ __forceinline__ void load_chunk(
    uint32_t sstage, const __nv_bfloat16* __restrict__ Ah,
    const __nv_bfloat16* __restrict__ Al, const __nv_bfloat16* __restrict__ Bh,
    const __nv_bfloat16* __restrict__ Bl, int bm, int bn, int k0, int K,
    int tid)
{
    const int rsub = tid >> 3;          // 0..31
    const int seg  = tid & 7;           // 16B segment
    #pragma unroll
    for (int i = 0; i < 16; i++) {
        const int t4  = i >> 2;
        const int row = (i & 3) * 32 + rsub;
        const __nv_bfloat16* sp =
            (t4 == 0) ? Ah : (t4 == 1) ? Al : (t4 == 2) ? Bh : Bl;
        const int gr = ((t4 < 2) ? bm : bn) + row;
        cpasync16(sstage + t4 * TILE_B + row * TSTRIDE + seg * 16,
                  sp + (size_t)gr * K + k0 + seg * 8);
    }
}

template <int EPI>
__global__ __launch_bounds__(256, 1) void mma_gemm(
    const __nv_bfloat16* __restrict__ Ah, const __nv_bfloat16* __restrict__ Al,
    const __nv_bfloat16* __restrict__ Bh, const __nv_bfloat16* __restrict__ Bl,
    const float* __restrict__ bias, const float* __restrict__ res,
    float* __restrict__ outF, __nv_bfloat16* __restrict__ outH,
    __nv_bfloat16* __restrict__ outL, int K, int N)
{
    extern __shared__ char smem[];
    const uint32_t sbase = smem_u32(smem);

    const int tid  = threadIdx.x;
    const int lane = tid & 31;
    const int wid  = tid >> 5;
    const int wm   = wid >> 2;          // 0..1
    const int wn   = wid & 3;           // 0..3
    const int bm   = blockIdx.y * 128;
    const int bn   = blockIdx.x * 128;

    float acc[4][4][4];
    #pragma unroll
    for (int i = 0; i < 4; i++)
        #pragma unroll
        for (int j = 0; j < 4; j++)
            #pragma unroll
            for (int q = 0; q < 4; q++) acc[i][j][q] = 0.f;

    // ldmatrix per-thread address pieces
    const int a_row = wm * 64 + (lane & 15);     // + mt*16
    const int a_cb  = (lane >> 4) * 16;          // + ks*32
    const int b_row = wn * 32 + (lane & 7);      // + nt*8
    const int b_cb  = ((lane >> 3) & 1) * 16;    // + ks*32

    const int NC = K >> 6;
    load_chunk(sbase, Ah, Al, Bh, Bl, bm, bn, 0, K, tid);
    CP_COMMIT();

    for (int c = 0; c < NC; c++) {
        if (c + 1 < NC) {
            load_chunk(sbase + ((c + 1) & 1) * STAGE_B, Ah, Al, Bh, Bl,
                       bm, bn, (c + 1) << 6, K, tid);
            CP_COMMIT();
            CP_WAIT(1);
        } else {
            CP_WAIT(0);
        }
        __syncthreads();

        const uint32_t st = sbase + (c & 1) * STAGE_B;
        const uint32_t aAh = st + 0 * TILE_B + a_row * TSTRIDE + a_cb;
        const uint32_t aAl = st + 1 * TILE_B + a_row * TSTRIDE + a_cb;
        const uint32_t aBh = st + 2 * TILE_B + b_row * TSTRIDE + b_cb;
        const uint32_t aBl = st + 3 * TILE_B + b_row * TSTRIDE + b_cb;

        #pragma unroll
        for (int ks = 0; ks < 4; ks++) {
            uint32_t ah[4][4], al[4][4], bh[4][2], bl[4][2];
            #pragma unroll
            for (int mt = 0; mt < 4; mt++) {
                ldmA(ah[mt], aAh + mt * (16 * TSTRIDE) + ks * 32);
                ldmA(al[mt], aAl + mt * (16 * TSTRIDE) + ks * 32);
            }
            #pragma unroll
            for (int nt = 0; nt < 4; nt++) {
                ldmB(bh[nt], aBh + nt * (8 * TSTRIDE) + ks * 32);
                ldmB(bl[nt], aBl + nt * (8 * TSTRIDE) + ks * 32);
            }
            #pragma unroll
            for (int mt = 0; mt < 4; mt++)
                #pragma unroll
                for (int nt = 0; nt < 4; nt++) {
                    mma16816(acc[mt][nt], ah[mt], bh[nt]);
                    mma16816(acc[mt][nt], ah[mt], bl[nt]);
                    mma16816(acc[mt][nt], al[mt], bh[nt]);
                }
        }
        __syncthreads();
    }

    // epilogue: thread owns rows (r, r+8), cols (c, c+1) per fragment
    const int r0 = bm + wm * 64 + (lane >> 2);
    const int c0 = bn + wn * 32 + 2 * (lane & 3);
    #pragma unroll
    for (int mt = 0; mt < 4; mt++) {
        #pragma unroll
        for (int nt = 0; nt < 4; nt++) {
            const int col = c0 + nt * 8;
            const float2 bb = *(const float2*)(bias + col);
            #pragma unroll
            for (int half = 0; half < 2; half++) {
                const int row = r0 + mt * 16 + half * 8;
                const size_t off = (size_t)row * N + col;
                float v0 = acc[mt][nt][half * 2 + 0] + bb.x;
                float v1 = acc[mt][nt][half * 2 + 1] + bb.y;
                if (EPI == 1) {
                    const float2 rr = *(const float2*)(res + off);
                    v0 += rr.x; v1 += rr.y;
                }
                if (EPI == 2) {
                    v0 = gelu_exact(v0); v1 = gelu_exact(v1);
                    __nv_bfloat16 h0, l0, h1, l1;
                    split_bf16(v0, h0, l0); split_bf16(v1, h1, l1);
                    const uint32_t hp = (uint32_t)__bfloat16_as_ushort(h0) |
                                        ((uint32_t)__bfloat16_as_ushort(h1) << 16);
                    const uint32_t lp = (uint32_t)__bfloat16_as_ushort(l0) |
                                        ((uint32_t)__bfloat16_as_ushort(l1) << 16);
                    *(uint32_t*)(outH + off) = hp;
                    *(uint32_t*)(outL + off) = lp;
                } else {
                    float2 o; o.x = v0; o.y = v1;
                    *(float2*)(outF + off) = o;
                }
            }
        }
    }
}

// ---------------------------------------------------------------------------
// Flash-style fp32 attention -> bf16 hi/lo output split. (unchanged math)
// ---------------------------------------------------------------------------
__global__ __launch_bounds__(256) void attn_kernel(
    const float* __restrict__ Q, const float* __restrict__ K,
    const float* __restrict__ V,
    __nv_bfloat16* __restrict__ Oh, __nv_bfloat16* __restrict__ Ol)
{
    constexpr int BQ = 64, BK = 32, D = HDIM;
    __shared__ float Qs[D][BQ];
    __shared__ float Ks[D][BK];
    __shared__ float Vs[BK][D];
    __shared__ float Ps[BQ][BK + 1];

    const int qt = blockIdx.x;
    const int h  = blockIdx.y;
    const int b  = blockIdx.z;
    const int tid = threadIdx.x;
    const int tx = tid & 15;
    const int ty = tid >> 4;

    const float scale = 0.125f;
    const size_t head_off = (size_t)h * HDIM;

    #pragma unroll
    for (int it = 0; it < 4; it++) {
        const int idx = it * 256 + tid;
        const int r = idx >> 4;
        const int c = (idx & 15) << 2;
        const float4 qv = *(const float4*)(
            Q + (size_t)(b * SEQLEN + qt * BQ + r) * CDIM + head_off + c);
        Qs[c + 0][r] = qv.x * scale;
        Qs[c + 1][r] = qv.y * scale;
        Qs[c + 2][r] = qv.z * scale;
        Qs[c + 3][r] = qv.w * scale;
    }

    float m_run[4], l_run[4], o_acc[4][4];
    #pragma unroll
    for (int i = 0; i < 4; i++) {
        m_run[i] = -1e30f; l_run[i] = 0.f;
        #pragma unroll
        for (int d = 0; d < 4; d++) o_acc[i][d] = 0.f;
    }
    __syncthreads();

    for (int kt = 0; kt < SEQLEN / BK; kt++) {
        #pragma unroll
        for (int it = 0; it < 2; it++) {
            const int idx = it * 256 + tid;
            const int r = idx >> 4;
            const int c = (idx & 15) << 2;
            const size_t gidx =
                (size_t)(b * SEQLEN + kt * BK + r) * CDIM + head_off + c;
            const float4 kv = *(const float4*)(K + gidx);
            Ks[c + 0][r] = kv.x; Ks[c + 1][r] = kv.y;
            Ks[c + 2][r] = kv.z; Ks[c + 3][r] = kv.w;
            *(float4*)&Vs[r][c] = *(const float4*)(V + gidx);
        }
        __syncthreads();

        float s[4][2] = {};
        #pragma unroll 8
        for (int d = 0; d < D; d++) {
            const float4 a = *(const float4*)&Qs[d][ty * 4];
            const float b0 = Ks[d][tx * 2 + 0];
            const float b1 = Ks[d][tx * 2 + 1];
            s[0][0] = fmaf(a.x, b0, s[0][0]); s[0][1] = fmaf(a.x, b1, s[0][1]);
            s[1][0] = fmaf(a.y, b0, s[1][0]); s[1][1] = fmaf(a.y, b1, s[1][1]);
            s[2][0] = fmaf(a.z, b0, s[2][0]); s[2][1] = fmaf(a.z, b1, s[2][1]);
            s[3][0] = fmaf(a.w, b0, s[3][0]); s[3][1] = fmaf(a.w, b1, s[3][1]);
        }

        #pragma unroll
        for (int i = 0; i < 4; i++) {
            float mx = fmaxf(s[i][0], s[i][1]);
            #pragma unroll
            for (int off = 8; off > 0; off >>= 1)
                mx = fmaxf(mx, __shfl_xor_sync(0xffffffffu, mx, off));
            const float mnew = fmaxf(m_run[i], mx);
            const float corr = __expf(m_run[i] - mnew);
            const float e0 = __expf(s[i][0] - mnew);
            const float e1 = __expf(s[i][1] - mnew);
            float sum = e0 + e1;
            #pragma unroll
            for (int off = 8; off > 0; off >>= 1)
                sum += __shfl_xor_sync(0xffffffffu, sum, off);
            l_run[i] = l_run[i] * corr + sum;
            m_run[i] = mnew;
            #pragma unroll
            for (int d = 0; d < 4; d++) o_acc[i][d] *= corr;
            Ps[ty * 4 + i][tx * 2 + 0] = e0;
            Ps[ty * 4 + i][tx * 2 + 1] = e1;
        }
        __syncthreads();

        #pragma unroll 8
        for (int j = 0; j < BK; j++) {
            const float4 vv = *(const float4*)&Vs[j][tx * 4];
            #pragma unroll
            for (int i = 0; i < 4; i++) {
                const float p = Ps[ty * 4 + i][j];
                o_acc[i][0] = fmaf(p, vv.x, o_acc[i][0]);
                o_acc[i][1] = fmaf(p, vv.y, o_acc[i][1]);
                o_acc[i][2] = fmaf(p, vv.z, o_acc[i][2]);
                o_acc[i][3] = fmaf(p, vv.w, o_acc[i][3]);
            }
        }
        __syncthreads();
    }

    #pragma unroll
    for (int i = 0; i < 4; i++) {
        const float inv = 1.0f / l_run[i];
        __align__(8) __nv_bfloat16 hh[4], ll[4];
        #pragma unroll
        for (int d = 0; d < 4; d++)
            split_bf16(o_acc[i][d] * inv, hh[d], ll[d]);
        const size_t oidx =
            (size_t)(b * SEQLEN + qt * BQ + ty * 4 + i) * CDIM + head_off + tx * 4;
        *(uint2*)(Oh + oidx) = *(uint2*)hh;
        *(uint2*)(Ol + oidx) = *(uint2*)ll;
    }
}

// ---------------------------------------------------------------------------
// kernel_launch
// ---------------------------------------------------------------------------
extern "C" void kernel_launch(void* const* d_in, const int* in_sizes, int n_in,
                              void* d_out, int out_size)
{
    const float* x   = (const float*)d_in[0];
    const float* g1  = (const float*)d_in[1];
    const float* b1  = (const float*)d_in[2];
    const float* Wq  = (const float*)d_in[3];
    const float* bq  = (const float*)d_in[4];
    const float* Wk  = (const float*)d_in[5];
    const float* bk  = (const float*)d_in[6];
    const float* Wv  = (const float*)d_in[7];
    const float* bv  = (const float*)d_in[8];
    const float* Wo  = (const float*)d_in[9];
    const float* bo  = (const float*)d_in[10];
    const float* g2  = (const float*)d_in[11];
    const float* b2  = (const float*)d_in[12];
    const float* W1  = (const float*)d_in[13];
    const float* bf1 = (const float*)d_in[14];
    const float* W2  = (const float*)d_in[15];
    const float* bf2 = (const float*)d_in[16];
    float* out = (float*)d_out;

    float *pq, *pk, *pv, *px1;
    __nv_bfloat16 *phh, *phl, *poh, *pol, *pfh, *pfl, *pwh, *pwl;
    cudaGetSymbolAddress((void**)&pq,  g_q);
    cudaGetSymbolAddress((void**)&pk,  g_k);
    cudaGetSymbolAddress((void**)&pv,  g_v);
    cudaGetSymbolAddress((void**)&px1, g_x1);
    cudaGetSymbolAddress((void**)&phh, g_hh);
    cudaGetSymbolAddress((void**)&phl, g_hl);
    cudaGetSymbolAddress((void**)&poh, g_oh);
    cudaGetSymbolAddress((void**)&pol, g_ol);
    cudaGetSymbolAddress((void**)&pfh, g_fh);
    cudaGetSymbolAddress((void**)&pfl, g_fl);
    cudaGetSymbolAddress((void**)&pwh, g_wh);
    cudaGetSymbolAddress((void**)&pwl, g_wl);

    cudaFuncSetAttribute(mma_gemm<0>, cudaFuncAttributeMaxDynamicSharedMemorySize, GSMEM);
    cudaFuncSetAttribute(mma_gemm<1>, cudaFuncAttributeMaxDynamicSharedMemorySize, GSMEM);
    cudaFuncSetAttribute(mma_gemm<2>, cudaFuncAttributeMaxDynamicSharedMemorySize, GSMEM);

    const dim3 gP (CDIM / 128,  MTOT / 128);   // (8, 32)
    const dim3 gF1(HIDDIM / 128, MTOT / 128);  // (32, 32)
    const dim3 gW1(CDIM / 32,  CDIM / 32);
    const dim3 gWa(HIDDIM / 32, CDIM / 32);    // W1: K=1024, N=4096
    const dim3 gWb(CDIM / 32,  HIDDIM / 32);   // W2: K=4096, N=1024

    // LN1 -> split
    ln_kernel<<<MTOT, 256>>>(x, g1, b1, phh, phl);
    // QKV projections
    wtrans_kernel<<<gW1, 256>>>(Wq, pwh, pwl, CDIM, CDIM);
    mma_gemm<0><<<gP, 256, GSMEM>>>(phh, phl, pwh, pwl, bq, nullptr,
                                    pq, nullptr, nullptr, CDIM, CDIM);
    wtrans_kernel<<<gW1, 256>>>(Wk, pwh, pwl, CDIM, CDIM);
    mma_gemm<0><<<gP, 256, GSMEM>>>(phh, phl, pwh, pwl, bk, nullptr,
                                    pk, nullptr, nullptr, CDIM, CDIM);
    wtrans_kernel<<<gW1, 256>>>(Wv, pwh, pwl, CDIM, CDIM);
    mma_gemm<0><<<gP, 256, GSMEM>>>(phh, phl, pwh, pwl, bv, nullptr,
                                    pv, nullptr, nullptr, CDIM, CDIM);
    // attention -> split
    attn_kernel<<<dim3(SEQLEN / 64, NHEADS, NBATCH), 256>>>(pq, pk, pv, poh, pol);
    // output projection + residual
    wtrans_kernel<<<gW1, 256>>>(Wo, pwh, pwl, CDIM, CDIM);
    mma_gemm<1><<<gP, 256, GSMEM>>>(poh, pol, pwh, pwl, bo, x,
                                    px1, nullptr, nullptr, CDIM, CDIM);
    // LN2 -> split
    ln_kernel<<<MTOT, 256>>>(px1, g2, b2, phh, phl);
    // FFN1 (GELU epilogue -> bf16 splits)
    wtrans_kernel<<<gWa, 256>>>(W1, pwh, pwl, CDIM, HIDDIM);
    mma_gemm<2><<<gF1, 256, GSMEM>>>(phh, phl, pwh, pwl, bf1, nullptr,
                                     nullptr, pfh, pfl, CDIM, HIDDIM);
    // FFN2 + residual -> output
    wtrans_kernel<<<gWb, 256>>>(W2, pwh, pwl, HIDDIM, CDIM);
    mma_gemm<1><<<gP, 256, GSMEM>>>(pfh, pfl, pwh, pwl, bf2, px1,
                                    out, nullptr, nullptr, HIDDIM, CDIM);
}

// round 7
// speedup vs baseline: 3.2271x; 1.8908x over previous
#include <cuda_runtime.h>
#include <cuda_bf16.h>
#include <math.h>
#include <stdint.h>

// ---------------------------------------------------------------------------
// TransformerBlock on GB300 (sm_103a; harness PTX target compute_103 => only
// portable features: mma.sync / ldmatrix / cp.async. No tcgen05/TMA/elect).
// Round 6: attention moved to mma.sync bf16 (FA2-style) with FMA-pipe exp2
// softmax (no MUFU). GEMMs keep the verified split-bf16 3-MMA scheme.
// ---------------------------------------------------------------------------

#define MTOT   4096
#define CDIM   1024
#define HIDDIM 4096
#define NBATCH 2
#define SEQLEN 2048
#define NHEADS 16
#define HDIM   64

// ------------------------------ scratch ------------------------------------
__device__ float g_x1[MTOT * CDIM];
__device__ __nv_bfloat16 g_hh[MTOT * CDIM], g_hl[MTOT * CDIM];   // LN out
__device__ __nv_bfloat16 g_qb[MTOT * CDIM];                      // Q bf16
__device__ __nv_bfloat16 g_kb[MTOT * CDIM];                      // K bf16
__device__ __nv_bfloat16 g_vb[MTOT * CDIM];                      // V bf16
__device__ __nv_bfloat16 g_oh[MTOT * CDIM], g_ol[MTOT * CDIM];   // attn out
__device__ __nv_bfloat16 g_fh[(size_t)MTOT * HIDDIM];            // FFN hidden
__device__ __nv_bfloat16 g_fl[(size_t)MTOT * HIDDIM];
__device__ __nv_bfloat16 g_wh[(size_t)HIDDIM * CDIM];            // W^T scratch
__device__ __nv_bfloat16 g_wl[(size_t)HIDDIM * CDIM];

// --------------------------- helpers ---------------------------------------
__device__ __forceinline__ uint32_t smem_u32(const void* p) {
    uint32_t a;
    asm("{ .reg .u64 t; cvta.to.shared.u64 t, %1; cvt.u32.u64 %0, t; }"
        : "=r"(a) : "l"(p));
    return a;
}
__device__ __forceinline__ void cpasync16(uint32_t saddr, const void* g) {
    asm volatile("cp.async.cg.shared.global [%0], [%1], 16;"
                 :: "r"(saddr), "l"(g));
}
#define CP_COMMIT() asm volatile("cp.async.commit_group;" ::: "memory")
#define CP_WAIT(n)  asm volatile("cp.async.wait_group %0;" :: "n"(n) : "memory")

__device__ __forceinline__ void ldmA(uint32_t* a, uint32_t addr) {
    asm volatile("ldmatrix.sync.aligned.m8n8.x4.shared.b16 {%0,%1,%2,%3}, [%4];"
        : "=r"(a[0]), "=r"(a[1]), "=r"(a[2]), "=r"(a[3]) : "r"(addr));
}
__device__ __forceinline__ void ldmB(uint32_t* b, uint32_t addr) {
    asm volatile("ldmatrix.sync.aligned.m8n8.x2.shared.b16 {%0,%1}, [%2];"
        : "=r"(b[0]), "=r"(b[1]) : "r"(addr));
}
__device__ __forceinline__ void ldmBT(uint32_t* b, uint32_t addr) {
    asm volatile("ldmatrix.sync.aligned.m8n8.x2.trans.shared.b16 {%0,%1}, [%2];"
        : "=r"(b[0]), "=r"(b[1]) : "r"(addr));
}
__device__ __forceinline__ void mma16816(float* d, const uint32_t* a,
                                         const uint32_t* b) {
    asm volatile(
        "mma.sync.aligned.m16n8k16.row.col.f32.bf16.bf16.f32 "
        "{%0,%1,%2,%3}, {%4,%5,%6,%7}, {%8,%9}, {%0,%1,%2,%3};"
        : "+f"(d[0]), "+f"(d[1]), "+f"(d[2]), "+f"(d[3])
        : "r"(a[0]), "r"(a[1]), "r"(a[2]), "r"(a[3]), "r"(b[0]), "r"(b[1]));
}
__device__ __forceinline__ uint32_t pack_bf16(float lo, float hi) {
    uint32_t r;
    asm("cvt.rn.bf16x2.f32 %0, %1, %2;" : "=r"(r) : "f"(hi), "f"(lo));
    return r;
}
__device__ __forceinline__ void split_bf16(float v, __nv_bfloat16& h,
                                           __nv_bfloat16& l) {
    h = __float2bfloat16(v);
    l = __float2bfloat16(v - __bfloat162float(h));
}
__device__ __forceinline__ float gelu_exact(float x) {
    return 0.5f * x * (1.0f + erff(x * 0.70710678118654752f));
}
// FMA-pipe 2^x (no MUFU): magic-number round + deg-5 poly + exponent add.
__device__ __forceinline__ float exp2_fast(float x) {
    x = fmaxf(x, -126.0f);
    const float z = x + 12582912.0f;                 // 1.5*2^23
    const int   i = __float_as_int(z) - 0x4B400000;
    const float f = x - (z - 12582912.0f);           // [-0.5, 0.5]
    float p =          1.3333558e-3f;
    p = fmaf(p, f, 9.6181291e-3f);
    p = fmaf(p, f, 5.5504109e-2f);
    p = fmaf(p, f, 2.4022651e-1f);
    p = fmaf(p, f, 6.9314718e-1f);
    p = fmaf(p, f, 1.0f);
    return __int_as_float(__float_as_int(p) + (i << 23));
}
#define C_SCALE 0.18033688f   // (1/sqrt(64)) * log2(e)

// ---------------------------------------------------------------------------
// LayerNorm -> bf16 hi/lo split. One block per row, 256 thr.
// ---------------------------------------------------------------------------
__global__ __launch_bounds__(256) void ln_kernel(
    const float* __restrict__ in, const float* __restrict__ gamma,
    const float* __restrict__ beta,
    __nv_bfloat16* __restrict__ oh, __nv_bfloat16* __restrict__ ol)
{
    const int row = blockIdx.x;
    const int t   = threadIdx.x;
    const float4 v = ((const float4*)(in + (size_t)row * CDIM))[t];

    float s  = v.x + v.y + v.z + v.w;
    float ss = v.x * v.x + v.y * v.y + v.z * v.z + v.w * v.w;
    #pragma unroll
    for (int o = 16; o > 0; o >>= 1) {
        s  += __shfl_xor_sync(0xffffffffu, s,  o);
        ss += __shfl_xor_sync(0xffffffffu, ss, o);
    }
    __shared__ float sh_s[8], sh_ss[8], sh_stat[2];
    const int w = t >> 5, lane = t & 31;
    if (lane == 0) { sh_s[w] = s; sh_ss[w] = ss; }
    __syncthreads();
    if (t == 0) {
        float ts = 0.f, tss = 0.f;
        #pragma unroll
        for (int i = 0; i < 8; i++) { ts += sh_s[i]; tss += sh_ss[i]; }
        const float mu  = ts * (1.0f / CDIM);
        const float var = tss * (1.0f / CDIM) - mu * mu;
        sh_stat[0] = mu; sh_stat[1] = rsqrtf(var + 1e-5f);
    }
    __syncthreads();
    const float mu = sh_stat[0], r = sh_stat[1];

    const float4 g4 = ((const float4*)gamma)[t];
    const float4 b4 = ((const float4*)beta)[t];
    float y[4];
    y[0] = (v.x - mu) * r * g4.x + b4.x;
    y[1] = (v.y - mu) * r * g4.y + b4.y;
    y[2] = (v.z - mu) * r * g4.z + b4.z;
    y[3] = (v.w - mu) * r * g4.w + b4.w;

    __align__(8) __nv_bfloat16 hh[4], ll[4];
    #pragma unroll
    for (int i = 0; i < 4; i++) split_bf16(y[i], hh[i], ll[i]);
    *(uint2*)(oh + (size_t)row * CDIM + t * 4) = *(uint2*)hh;
    *(uint2*)(ol + (size_t)row * CDIM + t * 4) = *(uint2*)ll;
}

// ---------------------------------------------------------------------------
// Weight transpose + bf16 split:  W[K,N] fp32 -> Th/Tl[N,K] bf16
// ---------------------------------------------------------------------------
__global__ __launch_bounds__(256) void wtrans_kernel(
    const float* __restrict__ W, __nv_bfloat16* __restrict__ Th,
    __nv_bfloat16* __restrict__ Tl, int K, int N)
{
    __shared__ float t[32][33];
    const int n0 = blockIdx.x * 32, k0 = blockIdx.y * 32;
    const int tx = threadIdx.x & 31, ty = threadIdx.x >> 5;
    #pragma unroll
    for (int i = ty; i < 32; i += 8)
        t[i][tx] = W[(size_t)(k0 + i) * N + n0 + tx];
    __syncthreads();
    #pragma unroll
    for (int i = ty; i < 32; i += 8) {
        const float v = t[tx][i];
        __nv_bfloat16 h, l;
        split_bf16(v, h, l);
        Th[(size_t)(n0 + i) * K + k0 + tx] = h;
        Tl[(size_t)(n0 + i) * K + k0 + tx] = l;
    }
}

// ---------------------------------------------------------------------------
// mma.sync GEMM (verified round-5 core):  out = (Ah+Al) @ (Bh+Bl)^T
// EPI: 0 bias->fp32, 1 bias+res->fp32, 2 bias+GELU->bf16 hi/lo, 3 bias->bf16
// ---------------------------------------------------------------------------
#define TSTRIDE 144
#define TILE_B  (128 * TSTRIDE)
#define STAGE_B (4 * TILE_B)
#define GSMEM   (2 * STAGE_B)

__device__ __forceinline__ void load_chunk(
    uint32_t sstage, const __nv_bfloat16* __restrict__ Ah,
    const __nv_bfloat16* __restrict__ Al, const __nv_bfloat16* __restrict__ Bh,
    const __nv_bfloat16* __restrict__ Bl, int bm, int bn, int k0, int K,
    int tid)
{
    const int rsub = tid >> 3;
    const int seg  = tid & 7;
    #pragma unroll
    for (int i = 0; i < 16; i++) {
        const int t4  = i >> 2;
        const int row = (i & 3) * 32 + rsub;
        const __nv_bfloat16* sp =
            (t4 == 0) ? Ah : (t4 == 1) ? Al : (t4 == 2) ? Bh : Bl;
        const int gr = ((t4 < 2) ? bm : bn) + row;
        cpasync16(sstage + t4 * TILE_B + row * TSTRIDE + seg * 16,
                  sp + (size_t)gr * K + k0 + seg * 8);
    }
}

template <int EPI>
__global__ __launch_bounds__(256, 1) void mma_gemm(
    const __nv_bfloat16* __restrict__ Ah, const __nv_bfloat16* __restrict__ Al,
    const __nv_bfloat16* __restrict__ Bh, const __nv_bfloat16* __restrict__ Bl,
    const float* __restrict__ bias, const float* __restrict__ res,
    float* __restrict__ outF, __nv_bfloat16* __restrict__ outH,
    __nv_bfloat16* __restrict__ outL, int K, int N)
{
    extern __shared__ char smem[];
    const uint32_t sbase = smem_u32(smem);

    const int tid  = threadIdx.x;
    const int lane = tid & 31;
    const int wid  = tid >> 5;
    const int wm   = wid >> 2;
    const int wn   = wid & 3;
    const int bm   = blockIdx.y * 128;
    const int bn   = blockIdx.x * 128;

    float acc[4][4][4];
    #pragma unroll
    for (int i = 0; i < 4; i++)
        #pragma unroll
        for (int j = 0; j < 4; j++)
            #pragma unroll
            for (int q = 0; q < 4; q++) acc[i][j][q] = 0.f;

    const int a_row = wm * 64 + (lane & 15);
    const int a_cb  = (lane >> 4) * 16;
    const int b_row = wn * 32 + (lane & 7);
    const int b_cb  = ((lane >> 3) & 1) * 16;

    const int NC = K >> 6;
    load_chunk(sbase, Ah, Al, Bh, Bl, bm, bn, 0, K, tid);
    CP_COMMIT();

    for (int c = 0; c < NC; c++) {
        if (c + 1 < NC) {
            load_chunk(sbase + ((c + 1) & 1) * STAGE_B, Ah, Al, Bh, Bl,
                       bm, bn, (c + 1) << 6, K, tid);
            CP_COMMIT();
            CP_WAIT(1);
        } else {
            CP_WAIT(0);
        }
        __syncthreads();

        const uint32_t st = sbase + (c & 1) * STAGE_B;
        const uint32_t aAh = st + 0 * TILE_B + a_row * TSTRIDE + a_cb;
        const uint32_t aAl = st + 1 * TILE_B + a_row * TSTRIDE + a_cb;
        const uint32_t aBh = st + 2 * TILE_B + b_row * TSTRIDE + b_cb;
        const uint32_t aBl = st + 3 * TILE_B + b_row * TSTRIDE + b_cb;

        #pragma unroll
        for (int ks = 0; ks < 4; ks++) {
            uint32_t ah[4][4], al[4][4], bh[4][2], bl[4][2];
            #pragma unroll
            for (int mt = 0; mt < 4; mt++) {
                ldmA(ah[mt], aAh + mt * (16 * TSTRIDE) + ks * 32);
                ldmA(al[mt], aAl + mt * (16 * TSTRIDE) + ks * 32);
            }
            #pragma unroll
            for (int nt = 0; nt < 4; nt++) {
                ldmB(bh[nt], aBh + nt * (8 * TSTRIDE) + ks * 32);
                ldmB(bl[nt], aBl + nt * (8 * TSTRIDE) + ks * 32);
            }
            #pragma unroll
            for (int mt = 0; mt < 4; mt++)
                #pragma unroll
                for (int nt = 0; nt < 4; nt++) {
                    mma16816(acc[mt][nt], ah[mt], bh[nt]);
                    mma16816(acc[mt][nt], ah[mt], bl[nt]);
                    mma16816(acc[mt][nt], al[mt], bh[nt]);
                }
        }
        __syncthreads();
    }

    const int r0 = bm + wm * 64 + (lane >> 2);
    const int c0 = bn + wn * 32 + 2 * (lane & 3);
    #pragma unroll
    for (int mt = 0; mt < 4; mt++) {
        #pragma unroll
        for (int nt = 0; nt < 4; nt++) {
            const int col = c0 + nt * 8;
            const float2 bb = *(const float2*)(bias + col);
            #pragma unroll
            for (int half = 0; half < 2; half++) {
                const int row = r0 + mt * 16 + half * 8;
                const size_t off = (size_t)row * N + col;
                float v0 = acc[mt][nt][half * 2 + 0] + bb.x;
                float v1 = acc[mt][nt][half * 2 + 1] + bb.y;
                if (EPI == 1) {
                    const float2 rr = *(const float2*)(res + off);
                    v0 += rr.x; v1 += rr.y;
                }
                if (EPI == 2) {
                    v0 = gelu_exact(v0); v1 = gelu_exact(v1);
                    __nv_bfloat16 h0, l0, h1, l1;
                    split_bf16(v0, h0, l0); split_bf16(v1, h1, l1);
                    *(uint32_t*)(outH + off) =
                        (uint32_t)__bfloat16_as_ushort(h0) |
                        ((uint32_t)__bfloat16_as_ushort(h1) << 16);
                    *(uint32_t*)(outL + off) =
                        (uint32_t)__bfloat16_as_ushort(l0) |
                        ((uint32_t)__bfloat16_as_ushort(l1) << 16);
                } else if (EPI == 3) {
                    *(uint32_t*)(outH + off) = pack_bf16(v0, v1);
                } else {
                    float2 o; o.x = v0; o.y = v1;
                    *(float2*)(outF + off) = o;
                }
            }
        }
    }
}

// ---------------------------------------------------------------------------
// mma.sync flash attention. Grid (SEQ/128, B*H), 256 thr (8 warps x 16 rows).
// BQ=128, BKV=64, D=64. bf16 QK^T and PV on tensor pipe, fp32 online softmax
// on the FMA pipe (exp2_fast, no MUFU). Double-buffered cp.async K/V.
// ---------------------------------------------------------------------------
#define AK_OFF    18432            // Q tile: 128 x 144B
#define AV_OFF    36864
#define AKV_STAGE 9216             // 64 x 144B
#define ASMEM     55296

__device__ __forceinline__ void attn_load_kv(
    uint32_t sb, const __nv_bfloat16* __restrict__ Kb,
    const __nv_bfloat16* __restrict__ Vb, int rowKV, int hoff,
    int stage, int kt, int tid)
{
    const int rb = rowKV + kt * 64;
    #pragma unroll
    for (int i = 0; i < 4; i++) {
        const int idx  = i * 256 + tid;
        const int half = idx >> 9;
        const int r    = (idx >> 3) & 63;
        const int seg  = idx & 7;
        const __nv_bfloat16* src = half ? Vb : Kb;
        const uint32_t dst = sb + (half ? AV_OFF : AK_OFF) +
                             stage * AKV_STAGE + r * 144 + seg * 16;
        cpasync16(dst, src + (size_t)(rb + r) * CDIM + hoff + seg * 8);
    }
}

__global__ __launch_bounds__(256, 2) void attn_mma(
    const __nv_bfloat16* __restrict__ Qb, const __nv_bfloat16* __restrict__ Kb,
    const __nv_bfloat16* __restrict__ Vb,
    __nv_bfloat16* __restrict__ Oh, __nv_bfloat16* __restrict__ Ol)
{
    extern __shared__ char smem[];
    const uint32_t sb = smem_u32(smem);
    const int tid = threadIdx.x, lane = tid & 31, wid = tid >> 5;
    const int qt   = blockIdx.x;
    const int b    = blockIdx.y >> 4, h = blockIdx.y & 15;
    const int rowQ  = b * SEQLEN + qt * 128;
    const int rowKV = b * SEQLEN;
    const int hoff  = h * HDIM;

    // G0: Q tile + KV tile 0
    #pragma unroll
    for (int i = 0; i < 4; i++) {
        const int idx = i * 256 + tid;
        const int r = idx >> 3, seg = idx & 7;
        cpasync16(sb + r * 144 + seg * 16,
                  Qb + (size_t)(rowQ + r) * CDIM + hoff + seg * 8);
    }
    attn_load_kv(sb, Kb, Vb, rowKV, hoff, 0, 0, tid);
    CP_COMMIT();
    // G1: KV tile 1
    attn_load_kv(sb, Kb, Vb, rowKV, hoff, 1, 1, tid);
    CP_COMMIT();

    CP_WAIT(1);
    __syncthreads();

    // Q fragments (held in registers for the whole kernel)
    uint32_t qf[4][4];
    {
        const uint32_t qa = sb + (wid * 16 + (lane & 15)) * 144 +
                            (lane >> 4) * 16;
        #pragma unroll
        for (int ks = 0; ks < 4; ks++) ldmA(qf[ks], qa + ks * 32);
    }

    float o[8][4];
    #pragma unroll
    for (int nt = 0; nt < 8; nt++)
        #pragma unroll
        for (int j = 0; j < 4; j++) o[nt][j] = 0.f;
    float mrun[2] = {-1e30f, -1e30f}, lrun[2] = {0.f, 0.f};

    const uint32_t koff_l = (lane & 7) * 144 + ((lane >> 3) & 1) * 16;
    const uint32_t voff_l = (lane & 15) * 144;
    constexpr int NKT = SEQLEN / 64;

    for (int kt = 0; kt < NKT; kt++) {
        if (kt > 0) {
            if (kt + 1 < NKT) { CP_WAIT(1); } else { CP_WAIT(0); }
            __syncthreads();
        }
        const int stage = kt & 1;
        const uint32_t skb = sb + AK_OFF + stage * AKV_STAGE;
        const uint32_t svb = sb + AV_OFF + stage * AKV_STAGE;

        // S = Q K^T (raw, fp32 acc)
        float sacc[8][4];
        #pragma unroll
        for (int nt = 0; nt < 8; nt++)
            #pragma unroll
            for (int j = 0; j < 4; j++) sacc[nt][j] = 0.f;
        #pragma unroll
        for (int ks = 0; ks < 4; ks++) {
            #pragma unroll
            for (int nt = 0; nt < 8; nt++) {
                uint32_t kf[2];
                ldmB(kf, skb + nt * (8 * 144) + koff_l + ks * 32);
                mma16816(sacc[nt], qf[ks], kf);
            }
        }

        // online softmax (scale folded: p = 2^(C*(s - m)))
        float corr[2];
        #pragma unroll
        for (int hf = 0; hf < 2; hf++) {
            const int i0 = hf * 2, i1 = hf * 2 + 1;
            float mx = fmaxf(sacc[0][i0], sacc[0][i1]);
            #pragma unroll
            for (int nt = 1; nt < 8; nt++)
                mx = fmaxf(mx, fmaxf(sacc[nt][i0], sacc[nt][i1]));
            mx = fmaxf(mx, __shfl_xor_sync(0xffffffffu, mx, 1));
            mx = fmaxf(mx, __shfl_xor_sync(0xffffffffu, mx, 2));
            const float mn = fmaxf(mrun[hf], mx);
            const float cm = C_SCALE * mn;
            corr[hf] = exp2_fast(fmaf(C_SCALE, mrun[hf], -cm));
            float sum = 0.f;
            #pragma unroll
            for (int nt = 0; nt < 8; nt++) {
                const float p0 = exp2_fast(fmaf(sacc[nt][i0], C_SCALE, -cm));
                const float p1 = exp2_fast(fmaf(sacc[nt][i1], C_SCALE, -cm));
                sacc[nt][i0] = p0; sacc[nt][i1] = p1;
                sum += p0 + p1;
            }
            sum += __shfl_xor_sync(0xffffffffu, sum, 1);
            sum += __shfl_xor_sync(0xffffffffu, sum, 2);
            lrun[hf] = lrun[hf] * corr[hf] + sum;
            mrun[hf] = mn;
        }

        // pack P accumulator fragments -> A fragments (no shuffles needed)
        uint32_t pa[4][4];
        #pragma unroll
        for (int t = 0; t < 4; t++) {
            pa[t][0] = pack_bf16(sacc[2 * t][0],     sacc[2 * t][1]);
            pa[t][1] = pack_bf16(sacc[2 * t][2],     sacc[2 * t][3]);
            pa[t][2] = pack_bf16(sacc[2 * t + 1][0], sacc[2 * t + 1][1]);
            pa[t][3] = pack_bf16(sacc[2 * t + 1][2], sacc[2 * t + 1][3]);
        }

        // rescale O, then O += P V  (V^T fragments via ldmatrix.trans)
        #pragma unroll
        for (int nt = 0; nt < 8; nt++) {
            o[nt][0] *= corr[0]; o[nt][1] *= corr[0];
            o[nt][2] *= corr[1]; o[nt][3] *= corr[1];
        }
        #pragma unroll
        for (int t = 0; t < 4; t++) {
            #pragma unroll
            for (int nt = 0; nt < 8; nt++) {
                uint32_t vf[2];
                ldmBT(vf, svb + t * (16 * 144) + voff_l + nt * 16);
                mma16816(o[nt], pa[t], vf);
            }
        }

        __syncthreads();
        if (kt + 2 < NKT) {
            attn_load_kv(sb, Kb, Vb, rowKV, hoff, stage, kt + 2, tid);
            CP_COMMIT();
        }
    }

    // normalize + bf16 hi/lo split store
    const float inv0 = 1.0f / lrun[0], inv1 = 1.0f / lrun[1];
    const int rg = rowQ + wid * 16 + (lane >> 2);
    const int cg = hoff + 2 * (lane & 3);
    #pragma unroll
    for (int nt = 0; nt < 8; nt++) {
        #pragma unroll
        for (int hf = 0; hf < 2; hf++) {
            const float inv = hf ? inv1 : inv0;
            const float v0 = o[nt][hf * 2 + 0] * inv;
            const float v1 = o[nt][hf * 2 + 1] * inv;
            __nv_bfloat16 h0, l0, h1, l1;
            split_bf16(v0, h0, l0); split_bf16(v1, h1, l1);
            const size_t off = (size_t)(rg + hf * 8) * CDIM + cg + nt * 8;
            *(uint32_t*)(Oh + off) =
                (uint32_t)__bfloat16_as_ushort(h0) |
                ((uint32_t)__bfloat16_as_ushort(h1) << 16);
            *(uint32_t*)(Ol + off) =
                (uint32_t)__bfloat16_as_ushort(l0) |
                ((uint32_t)__bfloat16_as_ushort(l1) << 16);
        }
    }
}

// ---------------------------------------------------------------------------
// kernel_launch
// ---------------------------------------------------------------------------
extern "C" void kernel_launch(void* const* d_in, const int* in_sizes, int n_in,
                              void* d_out, int out_size)
{
    const float* x   = (const float*)d_in[0];
    const float* g1  = (const float*)d_in[1];
    const float* b1  = (const float*)d_in[2];
    const float* Wq  = (const float*)d_in[3];
    const float* bq  = (const float*)d_in[4];
    const float* Wk  = (const float*)d_in[5];
    const float* bk  = (const float*)d_in[6];
    const float* Wv  = (const float*)d_in[7];
    const float* bv  = (const float*)d_in[8];
    const float* Wo  = (const float*)d_in[9];
    const float* bo  = (const float*)d_in[10];
    const float* g2  = (const float*)d_in[11];
    const float* b2  = (const float*)d_in[12];
    const float* W1  = (const float*)d_in[13];
    const float* bf1 = (const float*)d_in[14];
    const float* W2  = (const float*)d_in[15];
    const float* bf2 = (const float*)d_in[16];
    float* out = (float*)d_out;

    float *px1;
    __nv_bfloat16 *phh, *phl, *pqb, *pkb, *pvb, *poh, *pol, *pfh, *pfl, *pwh, *pwl;
    cudaGetSymbolAddress((void**)&px1, g_x1);
    cudaGetSymbolAddress((void**)&phh, g_hh);
    cudaGetSymbolAddress((void**)&phl, g_hl);
    cudaGetSymbolAddress((void**)&pqb, g_qb);
    cudaGetSymbolAddress((void**)&pkb, g_kb);
    cudaGetSymbolAddress((void**)&pvb, g_vb);
    cudaGetSymbolAddress((void**)&poh, g_oh);
    cudaGetSymbolAddress((void**)&pol, g_ol);
    cudaGetSymbolAddress((void**)&pfh, g_fh);
    cudaGetSymbolAddress((void**)&pfl, g_fl);
    cudaGetSymbolAddress((void**)&pwh, g_wh);
    cudaGetSymbolAddress((void**)&pwl, g_wl);

    cudaFuncSetAttribute(mma_gemm<0>, cudaFuncAttributeMaxDynamicSharedMemorySize, GSMEM);
    cudaFuncSetAttribute(mma_gemm<1>, cudaFuncAttributeMaxDynamicSharedMemorySize, GSMEM);
    cudaFuncSetAttribute(mma_gemm<2>, cudaFuncAttributeMaxDynamicSharedMemorySize, GSMEM);
    cudaFuncSetAttribute(mma_gemm<3>, cudaFuncAttributeMaxDynamicSharedMemorySize, GSMEM);
    cudaFuncSetAttribute(attn_mma,    cudaFuncAttributeMaxDynamicSharedMemorySize, ASMEM);

    const dim3 gP (CDIM / 128,  MTOT / 128);   // (8, 32)
    const dim3 gF1(HIDDIM / 128, MTOT / 128);  // (32, 32)
    const dim3 gW1(CDIM / 32,  CDIM / 32);
    const dim3 gWa(HIDDIM / 32, CDIM / 32);    // W1: K=1024, N=4096
    const dim3 gWb(CDIM / 32,  HIDDIM / 32);   // W2: K=4096, N=1024

    // LN1 -> split
    ln_kernel<<<MTOT, 256>>>(x, g1, b1, phh, phl);
    // QKV projections -> bf16 (attention operands)
    wtrans_kernel<<<gW1, 256>>>(Wq, pwh, pwl, CDIM, CDIM);
    mma_gemm<3><<<gP, 256, GSMEM>>>(phh, phl, pwh, pwl, bq, nullptr,
                                    nullptr, pqb, nullptr, CDIM, CDIM);
    wtrans_kernel<<<gW1, 256>>>(Wk, pwh, pwl, CDIM, CDIM);
    mma_gemm<3><<<gP, 256, GSMEM>>>(phh, phl, pwh, pwl, bk, nullptr,
                                    nullptr, pkb, nullptr, CDIM, CDIM);
    wtrans_kernel<<<gW1, 256>>>(Wv, pwh, pwl, CDIM, CDIM);
    mma_gemm<3><<<gP, 256, GSMEM>>>(phh, phl, pwh, pwl, bv, nullptr,
                                    nullptr, pvb, nullptr, CDIM, CDIM);
    // attention (tensor pipe + FMA softmax) -> bf16 hi/lo
    attn_mma<<<dim3(SEQLEN / 128, NBATCH * NHEADS), 256, ASMEM>>>(
        pqb, pkb, pvb, poh, pol);
    // output projection + residual
    wtrans_kernel<<<gW1, 256>>>(Wo, pwh, pwl, CDIM, CDIM);
    mma_gemm<1><<<gP, 256, GSMEM>>>(poh, pol, pwh, pwl, bo, x,
                                    px1, nullptr, nullptr, CDIM, CDIM);
    // LN2 -> split
    ln_kernel<<<MTOT, 256>>>(px1, g2, b2, phh, phl);
    // FFN1 (GELU -> bf16 splits)
    wtrans_kernel<<<gWa, 256>>>(W1, pwh, pwl, CDIM, HIDDIM);
    mma_gemm<2><<<gF1, 256, GSMEM>>>(phh, phl, pwh, pwl, bf1, nullptr,
                                     nullptr, pfh, pfl, CDIM, HIDDIM);
    // FFN2 + residual -> output
    wtrans_kernel<<<gWb, 256>>>(W2, pwh, pwl, HIDDIM, CDIM);
    mma_gemm<1><<<gP, 256, GSMEM>>>(pfh, pfl, pwh, pwl, bf2, px1,
                                    out, nullptr, nullptr, HIDDIM, CDIM);
}

// round 8
// speedup vs baseline: 4.5011x; 1.3948x over previous
#include <cuda_runtime.h>
#include <cuda_fp16.h>
#include <math.h>
#include <stdint.h>

// ---------------------------------------------------------------------------
// TransformerBlock on GB300 (sm_103a; PTX target compute_103 => portable
// features only: mma.sync / ldmatrix / cp.async).
// Round 7: fp16 arithmetic everywhere on the tensor path.
//   GEMM: A split (Ah+Al fp16, exact to ~2^-22) x single fp16 weight
//         => 2 MMAs per fragment (was 3 bf16), err ~1.2e-4.
//   3-stage cp.async pipeline, one barrier per K-chunk.
//   Fused QKV GEMM (N=3072, packed output), fused weight transposes.
//   Attention: fp16 mma FA2 (more accurate than round-6 bf16), exp2 softmax.
// ---------------------------------------------------------------------------

#define MTOT   4096
#define CDIM   1024
#define HIDDIM 4096
#define NBATCH 2
#define SEQLEN 2048
#define NHEADS 16
#define HDIM   64
#define QKV_ST 3072

// ------------------------------ scratch ------------------------------------
__device__ float  g_x1[MTOT * CDIM];
__device__ __half g_hh[MTOT * CDIM], g_hl[MTOT * CDIM];      // LN out split
__device__ __half g_qkv[(size_t)MTOT * QKV_ST];              // packed Q|K|V
__device__ __half g_oh[MTOT * CDIM], g_ol[MTOT * CDIM];      // attn out split
__device__ __half g_fh[(size_t)MTOT * HIDDIM];               // FFN hidden split
__device__ __half g_fl[(size_t)MTOT * HIDDIM];
__device__ __half g_wqkv[(size_t)3 * CDIM * CDIM];           // W^T packed qkv
__device__ __half g_wo[(size_t)CDIM * CDIM];
__device__ __half g_w1t[(size_t)HIDDIM * CDIM];
__device__ __half g_w2t[(size_t)CDIM * HIDDIM];

// --------------------------- helpers ---------------------------------------
__device__ __forceinline__ uint32_t smem_u32(const void* p) {
    uint32_t a;
    asm("{ .reg .u64 t; cvta.to.shared.u64 t, %1; cvt.u32.u64 %0, t; }"
        : "=r"(a) : "l"(p));
    return a;
}
__device__ __forceinline__ void cpasync16(uint32_t saddr, const void* g) {
    asm volatile("cp.async.cg.shared.global [%0], [%1], 16;"
                 :: "r"(saddr), "l"(g));
}
#define CP_COMMIT() asm volatile("cp.async.commit_group;" ::: "memory")
#define CP_WAIT(n)  asm volatile("cp.async.wait_group %0;" :: "n"(n) : "memory")

__device__ __forceinline__ void ldmA(uint32_t* a, uint32_t addr) {
    asm volatile("ldmatrix.sync.aligned.m8n8.x4.shared.b16 {%0,%1,%2,%3}, [%4];"
        : "=r"(a[0]), "=r"(a[1]), "=r"(a[2]), "=r"(a[3]) : "r"(addr));
}
__device__ __forceinline__ void ldmB(uint32_t* b, uint32_t addr) {
    asm volatile("ldmatrix.sync.aligned.m8n8.x2.shared.b16 {%0,%1}, [%2];"
        : "=r"(b[0]), "=r"(b[1]) : "r"(addr));
}
__device__ __forceinline__ void ldmBT(uint32_t* b, uint32_t addr) {
    asm volatile("ldmatrix.sync.aligned.m8n8.x2.trans.shared.b16 {%0,%1}, [%2];"
        : "=r"(b[0]), "=r"(b[1]) : "r"(addr));
}
__device__ __forceinline__ void mmaF16(float* d, const uint32_t* a,
                                       const uint32_t* b) {
    asm volatile(
        "mma.sync.aligned.m16n8k16.row.col.f32.f16.f16.f32 "
        "{%0,%1,%2,%3}, {%4,%5,%6,%7}, {%8,%9}, {%0,%1,%2,%3};"
        : "+f"(d[0]), "+f"(d[1]), "+f"(d[2]), "+f"(d[3])
        : "r"(a[0]), "r"(a[1]), "r"(a[2]), "r"(a[3]), "r"(b[0]), "r"(b[1]));
}
__device__ __forceinline__ uint32_t pack_f16(float lo, float hi) {
    uint32_t r;
    asm("cvt.rn.f16x2.f32 %0, %1, %2;" : "=r"(r) : "f"(hi), "f"(lo));
    return r;
}
__device__ __forceinline__ void split_f16(float v, __half& h, __half& l) {
    h = __float2half_rn(v);
    l = __float2half_rn(v - __half2float(h));
}
__device__ __forceinline__ float gelu_exact(float x) {
    return 0.5f * x * (1.0f + erff(x * 0.70710678118654752f));
}
// FMA-pipe 2^x (no MUFU).
__device__ __forceinline__ float exp2_fast(float x) {
    x = fmaxf(x, -126.0f);
    const float z = x + 12582912.0f;
    const int   i = __float_as_int(z) - 0x4B400000;
    const float f = x - (z - 12582912.0f);
    float p =          1.3333558e-3f;
    p = fmaf(p, f, 9.6181291e-3f);
    p = fmaf(p, f, 5.5504109e-2f);
    p = fmaf(p, f, 2.4022651e-1f);
    p = fmaf(p, f, 6.9314718e-1f);
    p = fmaf(p, f, 1.0f);
    return __int_as_float(__float_as_int(p) + (i << 23));
}
#define C_SCALE 0.18033688f   // (1/sqrt(64)) * log2(e)

// ---------------------------------------------------------------------------
// LayerNorm -> fp16 hi/lo split. One block per row, 256 thr.
// ---------------------------------------------------------------------------
__global__ __launch_bounds__(256) void ln_kernel(
    const float* __restrict__ in, const float* __restrict__ gamma,
    const float* __restrict__ beta,
    __half* __restrict__ oh, __half* __restrict__ ol)
{
    const int row = blockIdx.x;
    const int t   = threadIdx.x;
    const float4 v = ((const float4*)(in + (size_t)row * CDIM))[t];

    float s  = v.x + v.y + v.z + v.w;
    float ss = v.x * v.x + v.y * v.y + v.z * v.z + v.w * v.w;
    #pragma unroll
    for (int o = 16; o > 0; o >>= 1) {
        s  += __shfl_xor_sync(0xffffffffu, s,  o);
        ss += __shfl_xor_sync(0xffffffffu, ss, o);
    }
    __shared__ float sh_s[8], sh_ss[8], sh_stat[2];
    const int w = t >> 5, lane = t & 31;
    if (lane == 0) { sh_s[w] = s; sh_ss[w] = ss; }
    __syncthreads();
    if (t == 0) {
        float ts = 0.f, tss = 0.f;
        #pragma unroll
        for (int i = 0; i < 8; i++) { ts += sh_s[i]; tss += sh_ss[i]; }
        const float mu  = ts * (1.0f / CDIM);
        const float var = tss * (1.0f / CDIM) - mu * mu;
        sh_stat[0] = mu; sh_stat[1] = rsqrtf(var + 1e-5f);
    }
    __syncthreads();
    const float mu = sh_stat[0], r = sh_stat[1];

    const float4 g4 = ((const float4*)gamma)[t];
    const float4 b4 = ((const float4*)beta)[t];
    float y[4];
    y[0] = (v.x - mu) * r * g4.x + b4.x;
    y[1] = (v.y - mu) * r * g4.y + b4.y;
    y[2] = (v.z - mu) * r * g4.z + b4.z;
    y[3] = (v.w - mu) * r * g4.w + b4.w;

    __align__(8) __half hh[4], ll[4];
    #pragma unroll
    for (int i = 0; i < 4; i++) split_f16(y[i], hh[i], ll[i]);
    *(uint2*)(oh + (size_t)row * CDIM + t * 4) = *(uint2*)hh;
    *(uint2*)(ol + (size_t)row * CDIM + t * 4) = *(uint2*)ll;
}

// ---------------------------------------------------------------------------
// Weight transposes -> fp16 single plane.
// wtrans4: Wq/Wk/Wv -> packed wqkv rows [0,3072), Wo -> wo. All 1024x1024.
// ---------------------------------------------------------------------------
__global__ __launch_bounds__(256) void wtrans4_kernel(
    const float* __restrict__ Wq, const float* __restrict__ Wk,
    const float* __restrict__ Wv, const float* __restrict__ Wo,
    __half* __restrict__ wqkv, __half* __restrict__ wo)
{
    __shared__ float t[32][33];
    const int z  = blockIdx.z;
    const float* W = (z == 0) ? Wq : (z == 1) ? Wk : (z == 2) ? Wv : Wo;
    __half* T = (z < 3) ? (wqkv + (size_t)z * CDIM * CDIM) : wo;
    const int n0 = blockIdx.x * 32, k0 = blockIdx.y * 32;
    const int tx = threadIdx.x & 31, ty = threadIdx.x >> 5;
    #pragma unroll
    for (int i = ty; i < 32; i += 8)
        t[i][tx] = W[(size_t)(k0 + i) * CDIM + n0 + tx];
    __syncthreads();
    #pragma unroll
    for (int i = ty; i < 32; i += 8)
        T[(size_t)(n0 + i) * CDIM + k0 + tx] = __float2half_rn(t[tx][i]);
}

__global__ __launch_bounds__(256) void wtrans_kernel(
    const float* __restrict__ W, __half* __restrict__ T, int K, int N)
{
    __shared__ float t[32][33];
    const int n0 = blockIdx.x * 32, k0 = blockIdx.y * 32;
    const int tx = threadIdx.x & 31, ty = threadIdx.x >> 5;
    #pragma unroll
    for (int i = ty; i < 32; i += 8)
        t[i][tx] = W[(size_t)(k0 + i) * N + n0 + tx];
    __syncthreads();
    #pragma unroll
    for (int i = ty; i < 32; i += 8)
        T[(size_t)(n0 + i) * K + k0 + tx] = __float2half_rn(t[tx][i]);
}

// ---------------------------------------------------------------------------
// fp16 split GEMM:  out[M,N] = (Ah+Al)[M,K] @ B[N,K]^T   (2 MMAs / frag)
// CTA 128x128, 8 warps, K-chunk 64, 3-stage cp.async, 1 barrier/chunk.
// EPI: 0 bias->f32, 1 bias+res->f32, 2 bias+GELU->fp16 hi/lo,
//      3 bias(seg-select)->fp16 packed (QKV, N=3072)
// ---------------------------------------------------------------------------
#define TSTRIDE 144
#define TILE_B  (128 * TSTRIDE)
#define STAGE_B (3 * TILE_B)          // Ah, Al, B
#define GSMEM   (3 * STAGE_B)         // 3 stages = 165888 B

__device__ __forceinline__ void load_chunk3(
    uint32_t sstage, const __half* __restrict__ Ah,
    const __half* __restrict__ Al, const __half* __restrict__ B,
    int bm, int bn, int k0, int K, int tid)
{
    const int rsub = tid >> 3;
    const int seg  = tid & 7;
    #pragma unroll
    for (int i = 0; i < 12; i++) {
        const int t3  = i >> 2;
        const int row = (i & 3) * 32 + rsub;
        const __half* sp = (t3 == 0) ? Ah : (t3 == 1) ? Al : B;
        const int gr = ((t3 < 2) ? bm : bn) + row;
        cpasync16(sstage + t3 * TILE_B + row * TSTRIDE + seg * 16,
                  sp + (size_t)gr * K + k0 + seg * 8);
    }
}

template <int EPI>
__global__ __launch_bounds__(256, 1) void mma_gemm(
    const __half* __restrict__ Ah, const __half* __restrict__ Al,
    const __half* __restrict__ B,
    const float* __restrict__ bias, const float* __restrict__ bias2,
    const float* __restrict__ bias3, const float* __restrict__ res,
    float* __restrict__ outF, __half* __restrict__ outH,
    __half* __restrict__ outL, int K, int N)
{
    extern __shared__ char smem[];
    const uint32_t sbase = smem_u32(smem);

    const int tid  = threadIdx.x;
    const int lane = tid & 31;
    const int wid  = tid >> 5;
    const int wm   = wid >> 2;
    const int wn   = wid & 3;
    const int bm   = blockIdx.y * 128;
    const int bn   = blockIdx.x * 128;

    float acc[4][4][4];
    #pragma unroll
    for (int i = 0; i < 4; i++)
        #pragma unroll
        for (int j = 0; j < 4; j++)
            #pragma unroll
            for (int q = 0; q < 4; q++) acc[i][j][q] = 0.f;

    const int a_row = wm * 64 + (lane & 15);
    const int a_cb  = (lane >> 4) * 16;
    const int b_row = wn * 32 + (lane & 7);
    const int b_cb  = ((lane >> 3) & 1) * 16;

    const int NC = K >> 6;
    load_chunk3(sbase,           Ah, Al, B, bm, bn,  0, K, tid); CP_COMMIT();
    load_chunk3(sbase + STAGE_B, Ah, Al, B, bm, bn, 64, K, tid); CP_COMMIT();

    int cs = 0;          // compute stage
    int ps = 2;          // prefetch stage
    for (int c = 0; c < NC; c++) {
        CP_WAIT(1);
        __syncthreads();

        const uint32_t st  = sbase + cs * STAGE_B;
        const uint32_t aAh = st + a_row * TSTRIDE + a_cb;
        const uint32_t aAl = st + TILE_B + a_row * TSTRIDE + a_cb;
        const uint32_t aB  = st + 2 * TILE_B + b_row * TSTRIDE + b_cb;

        #pragma unroll
        for (int ks = 0; ks < 4; ks++) {
            uint32_t ah[4][4], al[4][4], bf[4][2];
            #pragma unroll
            for (int mt = 0; mt < 4; mt++) {
                ldmA(ah[mt], aAh + mt * (16 * TSTRIDE) + ks * 32);
                ldmA(al[mt], aAl + mt * (16 * TSTRIDE) + ks * 32);
            }
            #pragma unroll
            for (int nt = 0; nt < 4; nt++)
                ldmB(bf[nt], aB + nt * (8 * TSTRIDE) + ks * 32);
            #pragma unroll
            for (int mt = 0; mt < 4; mt++)
                #pragma unroll
                for (int nt = 0; nt < 4; nt++) {
                    mmaF16(acc[mt][nt], ah[mt], bf[nt]);
                    mmaF16(acc[mt][nt], al[mt], bf[nt]);
                }
        }

        if (c + 2 < NC)
            load_chunk3(sbase + ps * STAGE_B, Ah, Al, B, bm, bn,
                        (c + 2) << 6, K, tid);
        CP_COMMIT();
        cs = (cs == 2) ? 0 : cs + 1;
        ps = (ps == 2) ? 0 : ps + 1;
    }

    // epilogue
    const float* bp = bias;
    int bofs = 0;
    if (EPI == 3) {
        bp   = (bn < 1024) ? bias : (bn < 2048) ? bias2 : bias3;
        bofs = bn & ~1023;
    }
    const int r0 = bm + wm * 64 + (lane >> 2);
    const int c0 = bn + wn * 32 + 2 * (lane & 3);
    #pragma unroll
    for (int mt = 0; mt < 4; mt++) {
        #pragma unroll
        for (int nt = 0; nt < 4; nt++) {
            const int col = c0 + nt * 8;
            const float2 bb = *(const float2*)(bp + col - bofs);
            #pragma unroll
            for (int half = 0; half < 2; half++) {
                const int row = r0 + mt * 16 + half * 8;
                const size_t off = (size_t)row * N + col;
                float v0 = acc[mt][nt][half * 2 + 0] + bb.x;
                float v1 = acc[mt][nt][half * 2 + 1] + bb.y;
                if (EPI == 1) {
                    const float2 rr = *(const float2*)(res + off);
                    v0 += rr.x; v1 += rr.y;
                }
                if (EPI == 2) {
                    v0 = gelu_exact(v0); v1 = gelu_exact(v1);
                    __half h0, l0, h1, l1;
                    split_f16(v0, h0, l0); split_f16(v1, h1, l1);
                    *(uint32_t*)(outH + off) =
                        (uint32_t)__half_as_ushort(h0) |
                        ((uint32_t)__half_as_ushort(h1) << 16);
                    *(uint32_t*)(outL + off) =
                        (uint32_t)__half_as_ushort(l0) |
                        ((uint32_t)__half_as_ushort(l1) << 16);
                } else if (EPI == 3) {
                    *(uint32_t*)(outH + off) = pack_f16(v0, v1);
                } else {
                    float2 o; o.x = v0; o.y = v1;
                    *(float2*)(outF + off) = o;
                }
            }
        }
    }
}

// ---------------------------------------------------------------------------
// fp16 mma flash attention. Grid (SEQ/128, B*H), 256 thr.
// Q/K/V read from packed qkv [row][3072] (Q:+0, K:+1024, V:+2048).
// ---------------------------------------------------------------------------
#define AK_OFF    18432
#define AV_OFF    36864
#define AKV_STAGE 9216
#define ASMEM     55296

__device__ __forceinline__ void attn_load_kv(
    uint32_t sb, const __half* __restrict__ qkv, int rowKV, int hoff,
    int stage, int kt, int tid)
{
    const int rb = rowKV + kt * 64;
    #pragma unroll
    for (int i = 0; i < 4; i++) {
        const int idx  = i * 256 + tid;
        const int half = idx >> 9;
        const int r    = (idx >> 3) & 63;
        const int seg  = idx & 7;
        const int coff = (half ? 2048 : 1024) + hoff;
        const uint32_t dst = sb + (half ? AV_OFF : AK_OFF) +
                             stage * AKV_STAGE + r * 144 + seg * 16;
        cpasync16(dst, qkv + (size_t)(rb + r) * QKV_ST + coff + seg * 8);
    }
}

__global__ __launch_bounds__(256, 2) void attn_mma(
    const __half* __restrict__ qkv,
    __half* __restrict__ Oh, __half* __restrict__ Ol)
{
    extern __shared__ char smem[];
    const uint32_t sb = smem_u32(smem);
    const int tid = threadIdx.x, lane = tid & 31, wid = tid >> 5;
    const int qt   = blockIdx.x;
    const int b    = blockIdx.y >> 4, h = blockIdx.y & 15;
    const int rowQ  = b * SEQLEN + qt * 128;
    const int rowKV = b * SEQLEN;
    const int hoff  = h * HDIM;

    #pragma unroll
    for (int i = 0; i < 4; i++) {
        const int idx = i * 256 + tid;
        const int r = idx >> 3, seg = idx & 7;
        cpasync16(sb + r * 144 + seg * 16,
                  qkv + (size_t)(rowQ + r) * QKV_ST + hoff + seg * 8);
    }
    attn_load_kv(sb, qkv, rowKV, hoff, 0, 0, tid);
    CP_COMMIT();
    attn_load_kv(sb, qkv, rowKV, hoff, 1, 1, tid);
    CP_COMMIT();

    CP_WAIT(1);
    __syncthreads();

    uint32_t qf[4][4];
    {
        const uint32_t qa = sb + (wid * 16 + (lane & 15)) * 144 +
                            (lane >> 4) * 16;
        #pragma unroll
        for (int ks = 0; ks < 4; ks++) ldmA(qf[ks], qa + ks * 32);
    }

    float o[8][4];
    #pragma unroll
    for (int nt = 0; nt < 8; nt++)
        #pragma unroll
        for (int j = 0; j < 4; j++) o[nt][j] = 0.f;
    float mrun[2] = {-1e30f, -1e30f}, lrun[2] = {0.f, 0.f};

    const uint32_t koff_l = (lane & 7) * 144 + ((lane >> 3) & 1) * 16;
    const uint32_t voff_l = (lane & 15) * 144;
    constexpr int NKT = SEQLEN / 64;

    for (int kt = 0; kt < NKT; kt++) {
        if (kt > 0) {
            if (kt + 1 < NKT) { CP_WAIT(1); } else { CP_WAIT(0); }
            __syncthreads();
        }
        const int stage = kt & 1;
        const uint32_t skb = sb + AK_OFF + stage * AKV_STAGE;
        const uint32_t svb = sb + AV_OFF + stage * AKV_STAGE;

        float sacc[8][4];
        #pragma unroll
        for (int nt = 0; nt < 8; nt++)
            #pragma unroll
            for (int j = 0; j < 4; j++) sacc[nt][j] = 0.f;
        #pragma unroll
        for (int ks = 0; ks < 4; ks++) {
            #pragma unroll
            for (int nt = 0; nt < 8; nt++) {
                uint32_t kf[2];
                ldmB(kf, skb + nt * (8 * 144) + koff_l + ks * 32);
                mmaF16(sacc[nt], qf[ks], kf);
            }
        }

        float corr[2];
        #pragma unroll
        for (int hf = 0; hf < 2; hf++) {
            const int i0 = hf * 2, i1 = hf * 2 + 1;
            float mx = fmaxf(sacc[0][i0], sacc[0][i1]);
            #pragma unroll
            for (int nt = 1; nt < 8; nt++)
                mx = fmaxf(mx, fmaxf(sacc[nt][i0], sacc[nt][i1]));
            mx = fmaxf(mx, __shfl_xor_sync(0xffffffffu, mx, 1));
            mx = fmaxf(mx, __shfl_xor_sync(0xffffffffu, mx, 2));
            const float mn = fmaxf(mrun[hf], mx);
            const float cm = C_SCALE * mn;
            corr[hf] = exp2_fast(fmaf(C_SCALE, mrun[hf], -cm));
            float sum = 0.f;
            #pragma unroll
            for (int nt = 0; nt < 8; nt++) {
                const float p0 = exp2_fast(fmaf(sacc[nt][i0], C_SCALE, -cm));
                const float p1 = exp2_fast(fmaf(sacc[nt][i1], C_SCALE, -cm));
                sacc[nt][i0] = p0; sacc[nt][i1] = p1;
                sum += p0 + p1;
            }
            sum += __shfl_xor_sync(0xffffffffu, sum, 1);
            sum += __shfl_xor_sync(0xffffffffu, sum, 2);
            lrun[hf] = lrun[hf] * corr[hf] + sum;
            mrun[hf] = mn;
        }

        uint32_t pa[4][4];
        #pragma unroll
        for (int t = 0; t < 4; t++) {
            pa[t][0] = pack_f16(sacc[2 * t][0],     sacc[2 * t][1]);
            pa[t][1] = pack_f16(sacc[2 * t][2],     sacc[2 * t][3]);
            pa[t][2] = pack_f16(sacc[2 * t + 1][0], sacc[2 * t + 1][1]);
            pa[t][3] = pack_f16(sacc[2 * t + 1][2], sacc[2 * t + 1][3]);
        }

        #pragma unroll
        for (int nt = 0; nt < 8; nt++) {
            o[nt][0] *= corr[0]; o[nt][1] *= corr[0];
            o[nt][2] *= corr[1]; o[nt][3] *= corr[1];
        }
        #pragma unroll
        for (int t = 0; t < 4; t++) {
            #pragma unroll
            for (int nt = 0; nt < 8; nt++) {
                uint32_t vf[2];
                ldmBT(vf, svb + t * (16 * 144) + voff_l + nt * 16);
                mmaF16(o[nt], pa[t], vf);
            }
        }

        __syncthreads();
        if (kt + 2 < NKT) {
            attn_load_kv(sb, qkv, rowKV, hoff, stage, kt + 2, tid);
            CP_COMMIT();
        }
    }

    const float inv0 = 1.0f / lrun[0], inv1 = 1.0f / lrun[1];
    const int rg = rowQ + wid * 16 + (lane >> 2);
    const int cg = hoff + 2 * (lane & 3);
    #pragma unroll
    for (int nt = 0; nt < 8; nt++) {
        #pragma unroll
        for (int hf = 0; hf < 2; hf++) {
            const float inv = hf ? inv1 : inv0;
            const float v0 = o[nt][hf * 2 + 0] * inv;
            const float v1 = o[nt][hf * 2 + 1] * inv;
            __half h0, l0, h1, l1;
            split_f16(v0, h0, l0); split_f16(v1, h1, l1);
            const size_t off = (size_t)(rg + hf * 8) * CDIM + cg + nt * 8;
            *(uint32_t*)(Oh + off) =
                (uint32_t)__half_as_ushort(h0) |
                ((uint32_t)__half_as_ushort(h1) << 16);
            *(uint32_t*)(Ol + off) =
                (uint32_t)__half_as_ushort(l0) |
                ((uint32_t)__half_as_ushort(l1) << 16);
        }
    }
}

// ---------------------------------------------------------------------------
// kernel_launch
// ---------------------------------------------------------------------------
extern "C" void kernel_launch(void* const* d_in, const int* in_sizes, int n_in,
                              void* d_out, int out_size)
{
    const float* x   = (const float*)d_in[0];
    const float* g1  = (const float*)d_in[1];
    const float* b1  = (const float*)d_in[2];
    const float* Wq  = (const float*)d_in[3];
    const float* bq  = (const float*)d_in[4];
    const float* Wk  = (const float*)d_in[5];
    const float* bk  = (const float*)d_in[6];
    const float* Wv  = (const float*)d_in[7];
    const float* bv  = (const float*)d_in[8];
    const float* Wo  = (const float*)d_in[9];
    const float* bo  = (const float*)d_in[10];
    const float* g2  = (const float*)d_in[11];
    const float* b2  = (const float*)d_in[12];
    const float* W1  = (const float*)d_in[13];
    const float* bf1 = (const float*)d_in[14];
    const float* W2  = (const float*)d_in[15];
    const float* bf2 = (const float*)d_in[16];
    float* out = (float*)d_out;

    float *px1;
    __half *phh, *phl, *pqkv, *poh, *pol, *pfh, *pfl, *pwqkv, *pwo, *pw1t, *pw2t;
    cudaGetSymbolAddress((void**)&px1,   g_x1);
    cudaGetSymbolAddress((void**)&phh,   g_hh);
    cudaGetSymbolAddress((void**)&phl,   g_hl);
    cudaGetSymbolAddress((void**)&pqkv,  g_qkv);
    cudaGetSymbolAddress((void**)&poh,   g_oh);
    cudaGetSymbolAddress((void**)&pol,   g_ol);
    cudaGetSymbolAddress((void**)&pfh,   g_fh);
    cudaGetSymbolAddress((void**)&pfl,   g_fl);
    cudaGetSymbolAddress((void**)&pwqkv, g_wqkv);
    cudaGetSymbolAddress((void**)&pwo,   g_wo);
    cudaGetSymbolAddress((void**)&pw1t,  g_w1t);
    cudaGetSymbolAddress((void**)&pw2t,  g_w2t);

    cudaFuncSetAttribute(mma_gemm<0>, cudaFuncAttributeMaxDynamicSharedMemorySize, GSMEM);
    cudaFuncSetAttribute(mma_gemm<1>, cudaFuncAttributeMaxDynamicSharedMemorySize, GSMEM);
    cudaFuncSetAttribute(mma_gemm<2>, cudaFuncAttributeMaxDynamicSharedMemorySize, GSMEM);
    cudaFuncSetAttribute(mma_gemm<3>, cudaFuncAttributeMaxDynamicSharedMemorySize, GSMEM);
    cudaFuncSetAttribute(attn_mma,    cudaFuncAttributeMaxDynamicSharedMemorySize, ASMEM);

    const dim3 gQKV(QKV_ST / 128, MTOT / 128);   // (24, 32)
    const dim3 gP  (CDIM / 128,   MTOT / 128);   // (8, 32)
    const dim3 gF1 (HIDDIM / 128, MTOT / 128);   // (32, 32)

    // weight prep (independent of activations)
    wtrans4_kernel<<<dim3(32, 32, 4), 256>>>(Wq, Wk, Wv, Wo, pwqkv, pwo);
    wtrans_kernel<<<dim3(HIDDIM / 32, CDIM / 32), 256>>>(W1, pw1t, CDIM, HIDDIM);
    wtrans_kernel<<<dim3(CDIM / 32, HIDDIM / 32), 256>>>(W2, pw2t, HIDDIM, CDIM);

    // LN1 -> split
    ln_kernel<<<MTOT, 256>>>(x, g1, b1, phh, phl);
    // fused QKV projection -> packed fp16
    mma_gemm<3><<<gQKV, 256, GSMEM>>>(phh, phl, pwqkv, bq, bk, bv, nullptr,
                                      nullptr, pqkv, nullptr, CDIM, QKV_ST);
    // attention -> fp16 hi/lo
    attn_mma<<<dim3(SEQLEN / 128, NBATCH * NHEADS), 256, ASMEM>>>(pqkv, poh, pol);
    // output projection + residual
    mma_gemm<1><<<gP, 256, GSMEM>>>(poh, pol, pwo, bo, nullptr, nullptr, x,
                                    px1, nullptr, nullptr, CDIM, CDIM);
    // LN2 -> split
    ln_kernel<<<MTOT, 256>>>(px1, g2, b2, phh, phl);
    // FFN1 (GELU -> fp16 hi/lo)
    mma_gemm<2><<<gF1, 256, GSMEM>>>(phh, phl, pw1t, bf1, nullptr, nullptr,
                                     nullptr, nullptr, pfh, pfl, CDIM, HIDDIM);
    // FFN2 + residual -> output
    mma_gemm<1><<<gP, 256, GSMEM>>>(pfh, pfl, pw2t, bf2, nullptr, nullptr, px1,
                                    out, nullptr, nullptr, HIDDIM, CDIM);
}

// round 9
// speedup vs baseline: 7.1727x; 1.5936x over previous
#include <cuda_runtime.h>
#include <cuda_fp16.h>
#include <math.h>
#include <stdint.h>

// ---------------------------------------------------------------------------
// TransformerBlock on GB300 (sm_103a; PTX target compute_103 => portable
// features only: mma.sync / ldmatrix / cp.async).
// Round 8: single fp16 plane everywhere (activation lo-plane dropped).
//   Evidence: rounds 6/7 both hit ~344 TF/s on mma.sync => HMMA-pipe bound;
//   only FLOP reduction helps. Issued GEMM FLOPs 206 -> 103 GF.
//   GEMM: 1 MMA per fragment, 2 tiles/stage, 3-stage cp.async, 2 CTAs/SM.
//   Error model: fp16 activation rounding ~2.8e-4 rel, attenuated into the
//   residual stream => predicted total ~2-3e-4 (gate 1e-3).
// ---------------------------------------------------------------------------

#define MTOT   4096
#define CDIM   1024
#define HIDDIM 4096
#define NBATCH 2
#define SEQLEN 2048
#define NHEADS 16
#define HDIM   64
#define QKV_ST 3072

// ------------------------------ scratch ------------------------------------
__device__ float  g_x1[MTOT * CDIM];
__device__ __half g_h  [MTOT * CDIM];                        // LN out fp16
__device__ __half g_qkv[(size_t)MTOT * QKV_ST];              // packed Q|K|V
__device__ __half g_o  [MTOT * CDIM];                        // attn out fp16
__device__ __half g_f  [(size_t)MTOT * HIDDIM];              // FFN hidden fp16
__device__ __half g_wqkv[(size_t)3 * CDIM * CDIM];           // W^T packed qkv
__device__ __half g_wo [(size_t)CDIM * CDIM];
__device__ __half g_w1t[(size_t)HIDDIM * CDIM];
__device__ __half g_w2t[(size_t)CDIM * HIDDIM];

// --------------------------- helpers ---------------------------------------
__device__ __forceinline__ uint32_t smem_u32(const void* p) {
    uint32_t a;
    asm("{ .reg .u64 t; cvta.to.shared.u64 t, %1; cvt.u32.u64 %0, t; }"
        : "=r"(a) : "l"(p));
    return a;
}
__device__ __forceinline__ void cpasync16(uint32_t saddr, const void* g) {
    asm volatile("cp.async.cg.shared.global [%0], [%1], 16;"
                 :: "r"(saddr), "l"(g));
}
#define CP_COMMIT() asm volatile("cp.async.commit_group;" ::: "memory")
#define CP_WAIT(n)  asm volatile("cp.async.wait_group %0;" :: "n"(n) : "memory")

__device__ __forceinline__ void ldmA(uint32_t* a, uint32_t addr) {
    asm volatile("ldmatrix.sync.aligned.m8n8.x4.shared.b16 {%0,%1,%2,%3}, [%4];"
        : "=r"(a[0]), "=r"(a[1]), "=r"(a[2]), "=r"(a[3]) : "r"(addr));
}
__device__ __forceinline__ void ldmB(uint32_t* b, uint32_t addr) {
    asm volatile("ldmatrix.sync.aligned.m8n8.x2.shared.b16 {%0,%1}, [%2];"
        : "=r"(b[0]), "=r"(b[1]) : "r"(addr));
}
__device__ __forceinline__ void ldmBT(uint32_t* b, uint32_t addr) {
    asm volatile("ldmatrix.sync.aligned.m8n8.x2.trans.shared.b16 {%0,%1}, [%2];"
        : "=r"(b[0]), "=r"(b[1]) : "r"(addr));
}
__device__ __forceinline__ void mmaF16(float* d, const uint32_t* a,
                                       const uint32_t* b) {
    asm volatile(
        "mma.sync.aligned.m16n8k16.row.col.f32.f16.f16.f32 "
        "{%0,%1,%2,%3}, {%4,%5,%6,%7}, {%8,%9}, {%0,%1,%2,%3};"
        : "+f"(d[0]), "+f"(d[1]), "+f"(d[2]), "+f"(d[3])
        : "r"(a[0]), "r"(a[1]), "r"(a[2]), "r"(a[3]), "r"(b[0]), "r"(b[1]));
}
__device__ __forceinline__ uint32_t pack_f16(float lo, float hi) {
    uint32_t r;
    asm("cvt.rn.f16x2.f32 %0, %1, %2;" : "=r"(r) : "f"(hi), "f"(lo));
    return r;
}
__device__ __forceinline__ float gelu_exact(float x) {
    return 0.5f * x * (1.0f + erff(x * 0.70710678118654752f));
}
// FMA-pipe 2^x (no MUFU).
__device__ __forceinline__ float exp2_fast(float x) {
    x = fmaxf(x, -126.0f);
    const float z = x + 12582912.0f;
    const int   i = __float_as_int(z) - 0x4B400000;
    const float f = x - (z - 12582912.0f);
    float p =          1.3333558e-3f;
    p = fmaf(p, f, 9.6181291e-3f);
    p = fmaf(p, f, 5.5504109e-2f);
    p = fmaf(p, f, 2.4022651e-1f);
    p = fmaf(p, f, 6.9314718e-1f);
    p = fmaf(p, f, 1.0f);
    return __int_as_float(__float_as_int(p) + (i << 23));
}
#define C_SCALE 0.18033688f   // (1/sqrt(64)) * log2(e)

// ---------------------------------------------------------------------------
// LayerNorm -> fp16. One block per row, 256 thr.
// ---------------------------------------------------------------------------
__global__ __launch_bounds__(256) void ln_kernel(
    const float* __restrict__ in, const float* __restrict__ gamma,
    const float* __restrict__ beta, __half* __restrict__ oh)
{
    const int row = blockIdx.x;
    const int t   = threadIdx.x;
    const float4 v = ((const float4*)(in + (size_t)row * CDIM))[t];

    float s  = v.x + v.y + v.z + v.w;
    float ss = v.x * v.x + v.y * v.y + v.z * v.z + v.w * v.w;
    #pragma unroll
    for (int o = 16; o > 0; o >>= 1) {
        s  += __shfl_xor_sync(0xffffffffu, s,  o);
        ss += __shfl_xor_sync(0xffffffffu, ss, o);
    }
    __shared__ float sh_s[8], sh_ss[8], sh_stat[2];
    const int w = t >> 5, lane = t & 31;
    if (lane == 0) { sh_s[w] = s; sh_ss[w] = ss; }
    __syncthreads();
    if (t == 0) {
        float ts = 0.f, tss = 0.f;
        #pragma unroll
        for (int i = 0; i < 8; i++) { ts += sh_s[i]; tss += sh_ss[i]; }
        const float mu  = ts * (1.0f / CDIM);
        const float var = tss * (1.0f / CDIM) - mu * mu;
        sh_stat[0] = mu; sh_stat[1] = rsqrtf(var + 1e-5f);
    }
    __syncthreads();
    const float mu = sh_stat[0], r = sh_stat[1];

    const float4 g4 = ((const float4*)gamma)[t];
    const float4 b4 = ((const float4*)beta)[t];
    const uint32_t p0 = pack_f16((v.x - mu) * r * g4.x + b4.x,
                                 (v.y - mu) * r * g4.y + b4.y);
    const uint32_t p1 = pack_f16((v.z - mu) * r * g4.z + b4.z,
                                 (v.w - mu) * r * g4.w + b4.w);
    uint2 o; o.x = p0; o.y = p1;
    *(uint2*)(oh + (size_t)row * CDIM + t * 4) = o;
}

// ---------------------------------------------------------------------------
// Weight transposes -> fp16.
// ---------------------------------------------------------------------------
__global__ __launch_bounds__(256) void wtrans4_kernel(
    const float* __restrict__ Wq, const float* __restrict__ Wk,
    const float* __restrict__ Wv, const float* __restrict__ Wo,
    __half* __restrict__ wqkv, __half* __restrict__ wo)
{
    __shared__ float t[32][33];
    const int z  = blockIdx.z;
    const float* W = (z == 0) ? Wq : (z == 1) ? Wk : (z == 2) ? Wv : Wo;
    __half* T = (z < 3) ? (wqkv + (size_t)z * CDIM * CDIM) : wo;
    const int n0 = blockIdx.x * 32, k0 = blockIdx.y * 32;
    const int tx = threadIdx.x & 31, ty = threadIdx.x >> 5;
    #pragma unroll
    for (int i = ty; i < 32; i += 8)
        t[i][tx] = W[(size_t)(k0 + i) * CDIM + n0 + tx];
    __syncthreads();
    #pragma unroll
    for (int i = ty; i < 32; i += 8)
        T[(size_t)(n0 + i) * CDIM + k0 + tx] = __float2half_rn(t[tx][i]);
}

__global__ __launch_bounds__(256) void wtrans_kernel(
    const float* __restrict__ W, __half* __restrict__ T, int K, int N)
{
    __shared__ float t[32][33];
    const int n0 = blockIdx.x * 32, k0 = blockIdx.y * 32;
    const int tx = threadIdx.x & 31, ty = threadIdx.x >> 5;
    #pragma unroll
    for (int i = ty; i < 32; i += 8)
        t[i][tx] = W[(size_t)(k0 + i) * N + n0 + tx];
    __syncthreads();
    #pragma unroll
    for (int i = ty; i < 32; i += 8)
        T[(size_t)(n0 + i) * K + k0 + tx] = __float2half_rn(t[tx][i]);
}

// ---------------------------------------------------------------------------
// fp16 GEMM:  out[M,N] = A[M,K] @ B[N,K]^T   (1 MMA / frag)
// CTA 128x128, 8 warps, K-chunk 64, 3-stage cp.async, 2 CTAs/SM.
// EPI: 0 bias->f32, 1 bias+res->f32, 2 bias+GELU->fp16,
//      3 bias(seg-select)->fp16 packed (QKV, N=3072)
// ---------------------------------------------------------------------------
#define TSTRIDE 144
#define TILE_B  (128 * TSTRIDE)       // 18432 B
#define STAGE_B (2 * TILE_B)          // A, B => 36864 B
#define GSMEM   (3 * STAGE_B)         // 110592 B

__device__ __forceinline__ void load_chunk2(
    uint32_t sstage, const __half* __restrict__ A,
    const __half* __restrict__ B, int bm, int bn, int k0, int K, int tid)
{
    const int rsub = tid >> 3;
    const int seg  = tid & 7;
    #pragma unroll
    for (int i = 0; i < 8; i++) {
        const int t2  = i >> 2;
        const int row = (i & 3) * 32 + rsub;
        const __half* sp = t2 ? B : A;
        const int gr = (t2 ? bn : bm) + row;
        cpasync16(sstage + t2 * TILE_B + row * TSTRIDE + seg * 16,
                  sp + (size_t)gr * K + k0 + seg * 8);
    }
}

template <int EPI>
__global__ __launch_bounds__(256, 2) void mma_gemm(
    const __half* __restrict__ A, const __half* __restrict__ B,
    const float* __restrict__ bias, const float* __restrict__ bias2,
    const float* __restrict__ bias3, const float* __restrict__ res,
    float* __restrict__ outF, __half* __restrict__ outH, int K, int N)
{
    extern __shared__ char smem[];
    const uint32_t sbase = smem_u32(smem);

    const int tid  = threadIdx.x;
    const int lane = tid & 31;
    const int wid  = tid >> 5;
    const int wm   = wid >> 2;
    const int wn   = wid & 3;
    const int bm   = blockIdx.y * 128;
    const int bn   = blockIdx.x * 128;

    float acc[4][4][4];
    #pragma unroll
    for (int i = 0; i < 4; i++)
        #pragma unroll
        for (int j = 0; j < 4; j++)
            #pragma unroll
            for (int q = 0; q < 4; q++) acc[i][j][q] = 0.f;

    const int a_row = wm * 64 + (lane & 15);
    const int a_cb  = (lane >> 4) * 16;
    const int b_row = wn * 32 + (lane & 7);
    const int b_cb  = ((lane >> 3) & 1) * 16;

    const int NC = K >> 6;
    load_chunk2(sbase,           A, B, bm, bn,  0, K, tid); CP_COMMIT();
    load_chunk2(sbase + STAGE_B, A, B, bm, bn, 64, K, tid); CP_COMMIT();

    int cs = 0, ps = 2;
    for (int c = 0; c < NC; c++) {
        CP_WAIT(1);
        __syncthreads();

        const uint32_t st = sbase + cs * STAGE_B;
        const uint32_t aA = st + a_row * TSTRIDE + a_cb;
        const uint32_t aB = st + TILE_B + b_row * TSTRIDE + b_cb;

        #pragma unroll
        for (int ks = 0; ks < 4; ks++) {
            uint32_t af[4][4], bf[4][2];
            #pragma unroll
            for (int mt = 0; mt < 4; mt++)
                ldmA(af[mt], aA + mt * (16 * TSTRIDE) + ks * 32);
            #pragma unroll
            for (int nt = 0; nt < 4; nt++)
                ldmB(bf[nt], aB + nt * (8 * TSTRIDE) + ks * 32);
            #pragma unroll
            for (int mt = 0; mt < 4; mt++)
                #pragma unroll
                for (int nt = 0; nt < 4; nt++)
                    mmaF16(acc[mt][nt], af[mt], bf[nt]);
        }

        if (c + 2 < NC)
            load_chunk2(sbase + ps * STAGE_B, A, B, bm, bn, (c + 2) << 6,
                        K, tid);
        CP_COMMIT();
        cs = (cs == 2) ? 0 : cs + 1;
        ps = (ps == 2) ? 0 : ps + 1;
    }

    // epilogue
    const float* bp = bias;
    int bofs = 0;
    if (EPI == 3) {
        bp   = (bn < 1024) ? bias : (bn < 2048) ? bias2 : bias3;
        bofs = bn & ~1023;
    }
    const int r0 = bm + wm * 64 + (lane >> 2);
    const int c0 = bn + wn * 32 + 2 * (lane & 3);
    #pragma unroll
    for (int mt = 0; mt < 4; mt++) {
        #pragma unroll
        for (int nt = 0; nt < 4; nt++) {
            const int col = c0 + nt * 8;
            const float2 bb = *(const float2*)(bp + col - bofs);
            #pragma unroll
            for (int half = 0; half < 2; half++) {
                const int row = r0 + mt * 16 + half * 8;
                const size_t off = (size_t)row * N + col;
                float v0 = acc[mt][nt][half * 2 + 0] + bb.x;
                float v1 = acc[mt][nt][half * 2 + 1] + bb.y;
                if (EPI == 1) {
                    const float2 rr = *(const float2*)(res + off);
                    v0 += rr.x; v1 += rr.y;
                }
                if (EPI == 2) {
                    v0 = gelu_exact(v0); v1 = gelu_exact(v1);
                    *(uint32_t*)(outH + off) = pack_f16(v0, v1);
                } else if (EPI == 3) {
                    *(uint32_t*)(outH + off) = pack_f16(v0, v1);
                } else {
                    float2 o; o.x = v0; o.y = v1;
                    *(float2*)(outF + off) = o;
                }
            }
        }
    }
}

// ---------------------------------------------------------------------------
// fp16 mma flash attention. Grid (SEQ/128, B*H), 256 thr.
// Q/K/V read from packed qkv [row][3072] (Q:+0, K:+1024, V:+2048).
// ---------------------------------------------------------------------------
#define AK_OFF    18432
#define AV_OFF    36864
#define AKV_STAGE 9216
#define ASMEM     55296

__device__ __forceinline__ void attn_load_kv(
    uint32_t sb, const __half* __restrict__ qkv, int rowKV, int hoff,
    int stage, int kt, int tid)
{
    const int rb = rowKV + kt * 64;
    #pragma unroll
    for (int i = 0; i < 4; i++) {
        const int idx  = i * 256 + tid;
        const int half = idx >> 9;
        const int r    = (idx >> 3) & 63;
        const int seg  = idx & 7;
        const int coff = (half ? 2048 : 1024) + hoff;
        const uint32_t dst = sb + (half ? AV_OFF : AK_OFF) +
                             stage * AKV_STAGE + r * 144 + seg * 16;
        cpasync16(dst, qkv + (size_t)(rb + r) * QKV_ST + coff + seg * 8);
    }
}

__global__ __launch_bounds__(256, 2) void attn_mma(
    const __half* __restrict__ qkv, __half* __restrict__ Oh)
{
    extern __shared__ char smem[];
    const uint32_t sb = smem_u32(smem);
    const int tid = threadIdx.x, lane = tid & 31, wid = tid >> 5;
    const int qt   = blockIdx.x;
    const int b    = blockIdx.y >> 4, h = blockIdx.y & 15;
    const int rowQ  = b * SEQLEN + qt * 128;
    const int rowKV = b * SEQLEN;
    const int hoff  = h * HDIM;

    #pragma unroll
    for (int i = 0; i < 4; i++) {
        const int idx = i * 256 + tid;
        const int r = idx >> 3, seg = idx & 7;
        cpasync16(sb + r * 144 + seg * 16,
                  qkv + (size_t)(rowQ + r) * QKV_ST + hoff + seg * 8);
    }
    attn_load_kv(sb, qkv, rowKV, hoff, 0, 0, tid);
    CP_COMMIT();
    attn_load_kv(sb, qkv, rowKV, hoff, 1, 1, tid);
    CP_COMMIT();

    CP_WAIT(1);
    __syncthreads();

    uint32_t qf[4][4];
    {
        const uint32_t qa = sb + (wid * 16 + (lane & 15)) * 144 +
                            (lane >> 4) * 16;
        #pragma unroll
        for (int ks = 0; ks < 4; ks++) ldmA(qf[ks], qa + ks * 32);
    }

    float o[8][4];
    #pragma unroll
    for (int nt = 0; nt < 8; nt++)
        #pragma unroll
        for (int j = 0; j < 4; j++) o[nt][j] = 0.f;
    float mrun[2] = {-1e30f, -1e30f}, lrun[2] = {0.f, 0.f};

    const uint32_t koff_l = (lane & 7) * 144 + ((lane >> 3) & 1) * 16;
    const uint32_t voff_l = (lane & 15) * 144;
    constexpr int NKT = SEQLEN / 64;

    for (int kt = 0; kt < NKT; kt++) {
        if (kt > 0) {
            if (kt + 1 < NKT) { CP_WAIT(1); } else { CP_WAIT(0); }
            __syncthreads();
        }
        const int stage = kt & 1;
        const uint32_t skb = sb + AK_OFF + stage * AKV_STAGE;
        const uint32_t svb = sb + AV_OFF + stage * AKV_STAGE;

        float sacc[8][4];
        #pragma unroll
        for (int nt = 0; nt < 8; nt++)
            #pragma unroll
            for (int j = 0; j < 4; j++) sacc[nt][j] = 0.f;
        #pragma unroll
        for (int ks = 0; ks < 4; ks++) {
            #pragma unroll
            for (int nt = 0; nt < 8; nt++) {
                uint32_t kf[2];
                ldmB(kf, skb + nt * (8 * 144) + koff_l + ks * 32);
                mmaF16(sacc[nt], qf[ks], kf);
            }
        }

        float corr[2];
        #pragma unroll
        for (int hf = 0; hf < 2; hf++) {
            const int i0 = hf * 2, i1 = hf * 2 + 1;
            float mx = fmaxf(sacc[0][i0], sacc[0][i1]);
            #pragma unroll
            for (int nt = 1; nt < 8; nt++)
                mx = fmaxf(mx, fmaxf(sacc[nt][i0], sacc[nt][i1]));
            mx = fmaxf(mx, __shfl_xor_sync(0xffffffffu, mx, 1));
            mx = fmaxf(mx, __shfl_xor_sync(0xffffffffu, mx, 2));
            const float mn = fmaxf(mrun[hf], mx);
            const float cm = C_SCALE * mn;
            corr[hf] = exp2_fast(fmaf(C_SCALE, mrun[hf], -cm));
            float sum = 0.f;
            #pragma unroll
            for (int nt = 0; nt < 8; nt++) {
                const float p0 = exp2_fast(fmaf(sacc[nt][i0], C_SCALE, -cm));
                const float p1 = exp2_fast(fmaf(sacc[nt][i1], C_SCALE, -cm));
                sacc[nt][i0] = p0; sacc[nt][i1] = p1;
                sum += p0 + p1;
            }
            sum += __shfl_xor_sync(0xffffffffu, sum, 1);
            sum += __shfl_xor_sync(0xffffffffu, sum, 2);
            lrun[hf] = lrun[hf] * corr[hf] + sum;
            mrun[hf] = mn;
        }

        uint32_t pa[4][4];
        #pragma unroll
        for (int t = 0; t < 4; t++) {
            pa[t][0] = pack_f16(sacc[2 * t][0],     sacc[2 * t][1]);
            pa[t][1] = pack_f16(sacc[2 * t][2],     sacc[2 * t][3]);
            pa[t][2] = pack_f16(sacc[2 * t + 1][0], sacc[2 * t + 1][1]);
            pa[t][3] = pack_f16(sacc[2 * t + 1][2], sacc[2 * t + 1][3]);
        }

        #pragma unroll
        for (int nt = 0; nt < 8; nt++) {
            o[nt][0] *= corr[0]; o[nt][1] *= corr[0];
            o[nt][2] *= corr[1]; o[nt][3] *= corr[1];
        }
        #pragma unroll
        for (int t = 0; t < 4; t++) {
            #pragma unroll
            for (int nt = 0; nt < 8; nt++) {
                uint32_t vf[2];
                ldmBT(vf, svb + t * (16 * 144) + voff_l + nt * 16);
                mmaF16(o[nt], pa[t], vf);
            }
        }

        __syncthreads();
        if (kt + 2 < NKT) {
            attn_load_kv(sb, qkv, rowKV, hoff, stage, kt + 2, tid);
            CP_COMMIT();
        }
    }

    const float inv0 = 1.0f / lrun[0], inv1 = 1.0f / lrun[1];
    const int rg = rowQ + wid * 16 + (lane >> 2);
    const int cg = hoff + 2 * (lane & 3);
    #pragma unroll
    for (int nt = 0; nt < 8; nt++) {
        #pragma unroll
        for (int hf = 0; hf < 2; hf++) {
            const float inv = hf ? inv1 : inv0;
            const size_t off = (size_t)(rg + hf * 8) * CDIM + cg + nt * 8;
            *(uint32_t*)(Oh + off) =
                pack_f16(o[nt][hf * 2 + 0] * inv, o[nt][hf * 2 + 1] * inv);
        }
    }
}

// ---------------------------------------------------------------------------
// kernel_launch
// ---------------------------------------------------------------------------
extern "C" void kernel_launch(void* const* d_in, const int* in_sizes, int n_in,
                              void* d_out, int out_size)
{
    const float* x   = (const float*)d_in[0];
    const float* g1  = (const float*)d_in[1];
    const float* b1  = (const float*)d_in[2];
    const float* Wq  = (const float*)d_in[3];
    const float* bq  = (const float*)d_in[4];
    const float* Wk  = (const float*)d_in[5];
    const float* bk  = (const float*)d_in[6];
    const float* Wv  = (const float*)d_in[7];
    const float* bv  = (const float*)d_in[8];
    const float* Wo  = (const float*)d_in[9];
    const float* bo  = (const float*)d_in[10];
    const float* g2  = (const float*)d_in[11];
    const float* b2  = (const float*)d_in[12];
    const float* W1  = (const float*)d_in[13];
    const float* bf1 = (const float*)d_in[14];
    const float* W2  = (const float*)d_in[15];
    const float* bf2 = (const float*)d_in[16];
    float* out = (float*)d_out;

    float *px1;
    __half *ph, *pqkv, *po, *pf, *pwqkv, *pwo, *pw1t, *pw2t;
    cudaGetSymbolAddress((void**)&px1,   g_x1);
    cudaGetSymbolAddress((void**)&ph,    g_h);
    cudaGetSymbolAddress((void**)&pqkv,  g_qkv);
    cudaGetSymbolAddress((void**)&po,    g_o);
    cudaGetSymbolAddress((void**)&pf,    g_f);
    cudaGetSymbolAddress((void**)&pwqkv, g_wqkv);
    cudaGetSymbolAddress((void**)&pwo,   g_wo);
    cudaGetSymbolAddress((void**)&pw1t,  g_w1t);
    cudaGetSymbolAddress((void**)&pw2t,  g_w2t);

    cudaFuncSetAttribute(mma_gemm<0>, cudaFuncAttributeMaxDynamicSharedMemorySize, GSMEM);
    cudaFuncSetAttribute(mma_gemm<1>, cudaFuncAttributeMaxDynamicSharedMemorySize, GSMEM);
    cudaFuncSetAttribute(mma_gemm<2>, cudaFuncAttributeMaxDynamicSharedMemorySize, GSMEM);
    cudaFuncSetAttribute(mma_gemm<3>, cudaFuncAttributeMaxDynamicSharedMemorySize, GSMEM);
    cudaFuncSetAttribute(attn_mma,    cudaFuncAttributeMaxDynamicSharedMemorySize, ASMEM);

    const dim3 gQKV(QKV_ST / 128, MTOT / 128);   // (24, 32)
    const dim3 gP  (CDIM / 128,   MTOT / 128);   // (8, 32)
    const dim3 gF1 (HIDDIM / 128, MTOT / 128);   // (32, 32)

    // weight prep
    wtrans4_kernel<<<dim3(32, 32, 4), 256>>>(Wq, Wk, Wv, Wo, pwqkv, pwo);
    wtrans_kernel<<<dim3(HIDDIM / 32, CDIM / 32), 256>>>(W1, pw1t, CDIM, HIDDIM);
    wtrans_kernel<<<dim3(CDIM / 32, HIDDIM / 32), 256>>>(W2, pw2t, HIDDIM, CDIM);

    // LN1
    ln_kernel<<<MTOT, 256>>>(x, g1, b1, ph);
    // fused QKV projection -> packed fp16
    mma_gemm<3><<<gQKV, 256, GSMEM>>>(ph, pwqkv, bq, bk, bv, nullptr,
                                      nullptr, pqkv, CDIM, QKV_ST);
    // attention
    attn_mma<<<dim3(SEQLEN / 128, NBATCH * NHEADS), 256, ASMEM>>>(pqkv, po);
    // output projection + residual
    mma_gemm<1><<<gP, 256, GSMEM>>>(po, pwo, bo, nullptr, nullptr, x,
                                    px1, nullptr, CDIM, CDIM);
    // LN2
    ln_kernel<<<MTOT, 256>>>(px1, g2, b2, ph);
    // FFN1 (GELU -> fp16)
    mma_gemm<2><<<gF1, 256, GSMEM>>>(ph, pw1t, bf1, nullptr, nullptr, nullptr,
                                     nullptr, pf, CDIM, HIDDIM);
    // FFN2 + residual -> output
    mma_gemm<1><<<gP, 256, GSMEM>>>(pf, pw2t, bf2, nullptr, nullptr, px1,
                                    out, nullptr, HIDDIM, CDIM);
}

// round 10
// speedup vs baseline: 7.3397x; 1.0233x over previous
#include <cuda_runtime.h>
#include <cuda_fp16.h>
#include <math.h>
#include <stdint.h>

// ---------------------------------------------------------------------------
// TransformerBlock on GB300 (sm_103a; PTX target compute_103 => portable
// features only: mma.sync / ldmatrix / cp.async).
// Round 9: overhead attack. Evidence: issued-FLOP rate pinned at ~344 TF/s
// across 3 rounds of different GEMM configs => HMMA pipe ceiling; compute
// floor ~400 us. This round: warp-per-row LN (register-resident, MLP=8),
// weight transposes moved to a forked side stream (captured fork/join) so
// they overlap LN1 / QKV / attention. GEMM + attention kernels unchanged.
// ---------------------------------------------------------------------------

#define MTOT   4096
#define CDIM   1024
#define HIDDIM 4096
#define NBATCH 2
#define SEQLEN 2048
#define NHEADS 16
#define HDIM   64
#define QKV_ST 3072

// ------------------------------ scratch ------------------------------------
__device__ float  g_x1[MTOT * CDIM];
__device__ __half g_h  [MTOT * CDIM];                        // LN out fp16
__device__ __half g_qkv[(size_t)MTOT * QKV_ST];              // packed Q|K|V
__device__ __half g_o  [MTOT * CDIM];                        // attn out fp16
__device__ __half g_f  [(size_t)MTOT * HIDDIM];              // FFN hidden fp16
__device__ __half g_wqkv[(size_t)3 * CDIM * CDIM];           // W^T packed qkv
__device__ __half g_wo [(size_t)CDIM * CDIM];
__device__ __half g_w1t[(size_t)HIDDIM * CDIM];
__device__ __half g_w2t[(size_t)CDIM * HIDDIM];

// --------------------------- helpers ---------------------------------------
__device__ __forceinline__ uint32_t smem_u32(const void* p) {
    uint32_t a;
    asm("{ .reg .u64 t; cvta.to.shared.u64 t, %1; cvt.u32.u64 %0, t; }"
        : "=r"(a) : "l"(p));
    return a;
}
__device__ __forceinline__ void cpasync16(uint32_t saddr, const void* g) {
    asm volatile("cp.async.cg.shared.global [%0], [%1], 16;"
                 :: "r"(saddr), "l"(g));
}
#define CP_COMMIT() asm volatile("cp.async.commit_group;" ::: "memory")
#define CP_WAIT(n)  asm volatile("cp.async.wait_group %0;" :: "n"(n) : "memory")

__device__ __forceinline__ void ldmA(uint32_t* a, uint32_t addr) {
    asm volatile("ldmatrix.sync.aligned.m8n8.x4.shared.b16 {%0,%1,%2,%3}, [%4];"
        : "=r"(a[0]), "=r"(a[1]), "=r"(a[2]), "=r"(a[3]) : "r"(addr));
}
__device__ __forceinline__ void ldmB(uint32_t* b, uint32_t addr) {
    asm volatile("ldmatrix.sync.aligned.m8n8.x2.shared.b16 {%0,%1}, [%2];"
        : "=r"(b[0]), "=r"(b[1]) : "r"(addr));
}
__device__ __forceinline__ void ldmBT(uint32_t* b, uint32_t addr) {
    asm volatile("ldmatrix.sync.aligned.m8n8.x2.trans.shared.b16 {%0,%1}, [%2];"
        : "=r"(b[0]), "=r"(b[1]) : "r"(addr));
}
__device__ __forceinline__ void mmaF16(float* d, const uint32_t* a,
                                       const uint32_t* b) {
    asm volatile(
        "mma.sync.aligned.m16n8k16.row.col.f32.f16.f16.f32 "
        "{%0,%1,%2,%3}, {%4,%5,%6,%7}, {%8,%9}, {%0,%1,%2,%3};"
        : "+f"(d[0]), "+f"(d[1]), "+f"(d[2]), "+f"(d[3])
        : "r"(a[0]), "r"(a[1]), "r"(a[2]), "r"(a[3]), "r"(b[0]), "r"(b[1]));
}
__device__ __forceinline__ uint32_t pack_f16(float lo, float hi) {
    uint32_t r;
    asm("cvt.rn.f16x2.f32 %0, %1, %2;" : "=r"(r) : "f"(hi), "f"(lo));
    return r;
}
__device__ __forceinline__ float gelu_exact(float x) {
    return 0.5f * x * (1.0f + erff(x * 0.70710678118654752f));
}
// FMA-pipe 2^x (no MUFU).
__device__ __forceinline__ float exp2_fast(float x) {
    x = fmaxf(x, -126.0f);
    const float z = x + 12582912.0f;
    const int   i = __float_as_int(z) - 0x4B400000;
    const float f = x - (z - 12582912.0f);
    float p =          1.3333558e-3f;
    p = fmaf(p, f, 9.6181291e-3f);
    p = fmaf(p, f, 5.5504109e-2f);
    p = fmaf(p, f, 2.4022651e-1f);
    p = fmaf(p, f, 6.9314718e-1f);
    p = fmaf(p, f, 1.0f);
    return __int_as_float(__float_as_int(p) + (i << 23));
}
#define C_SCALE 0.18033688f   // (1/sqrt(64)) * log2(e)

// ---------------------------------------------------------------------------
// LayerNorm -> fp16. Warp-per-row, register-resident (MLP=8, no smem/bars).
// 256 thr = 8 rows per block, grid MTOT/8.
// ---------------------------------------------------------------------------
__global__ __launch_bounds__(256) void ln_kernel(
    const float* __restrict__ in, const float* __restrict__ gamma,
    const float* __restrict__ beta, __half* __restrict__ oh)
{
    const int lane = threadIdx.x & 31;
    const int row  = blockIdx.x * 8 + (threadIdx.x >> 5);
    const float4* rp = (const float4*)(in + (size_t)row * CDIM);

    float4 v[8];
    #pragma unroll
    for (int i = 0; i < 8; i++) v[i] = rp[lane + 32 * i];

    float s = 0.f, ss = 0.f;
    #pragma unroll
    for (int i = 0; i < 8; i++) {
        s  += v[i].x + v[i].y + v[i].z + v[i].w;
        ss += v[i].x * v[i].x + v[i].y * v[i].y +
              v[i].z * v[i].z + v[i].w * v[i].w;
    }
    #pragma unroll
    for (int o = 16; o > 0; o >>= 1) {
        s  += __shfl_xor_sync(0xffffffffu, s,  o);
        ss += __shfl_xor_sync(0xffffffffu, ss, o);
    }
    const float mu = s * (1.0f / CDIM);
    const float r  = rsqrtf(ss * (1.0f / CDIM) - mu * mu + 1e-5f);

    uint2* op = (uint2*)(oh + (size_t)row * CDIM);
    #pragma unroll
    for (int i = 0; i < 8; i++) {
        const float4 g4 = ((const float4*)gamma)[lane + 32 * i];
        const float4 b4 = ((const float4*)beta )[lane + 32 * i];
        uint2 o;
        o.x = pack_f16((v[i].x - mu) * r * g4.x + b4.x,
                       (v[i].y - mu) * r * g4.y + b4.y);
        o.y = pack_f16((v[i].z - mu) * r * g4.z + b4.z,
                       (v[i].w - mu) * r * g4.w + b4.w);
        op[lane + 32 * i] = o;
    }
}

// ---------------------------------------------------------------------------
// Weight transposes -> fp16 (run on side stream, off the critical path).
// ---------------------------------------------------------------------------
__global__ __launch_bounds__(256) void wtrans4_kernel(
    const float* __restrict__ Wq, const float* __restrict__ Wk,
    const float* __restrict__ Wv, const float* __restrict__ Wo,
    __half* __restrict__ wqkv, __half* __restrict__ wo)
{
    __shared__ float t[32][33];
    const int z  = blockIdx.z;
    const float* W = (z == 0) ? Wq : (z == 1) ? Wk : (z == 2) ? Wv : Wo;
    __half* T = (z < 3) ? (wqkv + (size_t)z * CDIM * CDIM) : wo;
    const int n0 = blockIdx.x * 32, k0 = blockIdx.y * 32;
    const int tx = threadIdx.x & 31, ty = threadIdx.x >> 5;
    #pragma unroll
    for (int i = ty; i < 32; i += 8)
        t[i][tx] = W[(size_t)(k0 + i) * CDIM + n0 + tx];
    __syncthreads();
    #pragma unroll
    for (int i = ty; i < 32; i += 8)
        T[(size_t)(n0 + i) * CDIM + k0 + tx] = __float2half_rn(t[tx][i]);
}

__global__ __launch_bounds__(256) void wtrans_kernel(
    const float* __restrict__ W, __half* __restrict__ T, int K, int N)
{
    __shared__ float t[32][33];
    const int n0 = blockIdx.x * 32, k0 = blockIdx.y * 32;
    const int tx = threadIdx.x & 31, ty = threadIdx.x >> 5;
    #pragma unroll
    for (int i = ty; i < 32; i += 8)
        t[i][tx] = W[(size_t)(k0 + i) * N + n0 + tx];
    __syncthreads();
    #pragma unroll
    for (int i = ty; i < 32; i += 8)
        T[(size_t)(n0 + i) * K + k0 + tx] = __float2half_rn(t[tx][i]);
}

// ---------------------------------------------------------------------------
// fp16 GEMM:  out[M,N] = A[M,K] @ B[N,K]^T   (1 MMA / frag)  [verified R8]
// CTA 128x128, 8 warps, K-chunk 64, 3-stage cp.async, 2 CTAs/SM.
// EPI: 0 bias->f32, 1 bias+res->f32, 2 bias+GELU->fp16,
//      3 bias(seg-select)->fp16 packed (QKV, N=3072)
// ---------------------------------------------------------------------------
#define TSTRIDE 144
#define TILE_B  (128 * TSTRIDE)       // 18432 B
#define STAGE_B (2 * TILE_B)          // A, B => 36864 B
#define GSMEM   (3 * STAGE_B)         // 110592 B

__device__ __forceinline__ void load_chunk2(
    uint32_t sstage, const __half* __restrict__ A,
    const __half* __restrict__ B, int bm, int bn, int k0, int K, int tid)
{
    const int rsub = tid >> 3;
    const int seg  = tid & 7;
    #pragma unroll
    for (int i = 0; i < 8; i++) {
        const int t2  = i >> 2;
        const int row = (i & 3) * 32 + rsub;
        const __half* sp = t2 ? B : A;
        const int gr = (t2 ? bn : bm) + row;
        cpasync16(sstage + t2 * TILE_B + row * TSTRIDE + seg * 16,
                  sp + (size_t)gr * K + k0 + seg * 8);
    }
}

template <int EPI>
__global__ __launch_bounds__(256, 2) void mma_gemm(
    const __half* __restrict__ A, const __half* __restrict__ B,
    const float* __restrict__ bias, const float* __restrict__ bias2,
    const float* __restrict__ bias3, const float* __restrict__ res,
    float* __restrict__ outF, __half* __restrict__ outH, int K, int N)
{
    extern __shared__ char smem[];
    const uint32_t sbase = smem_u32(smem);

    const int tid  = threadIdx.x;
    const int lane = tid & 31;
    const int wid  = tid >> 5;
    const int wm   = wid >> 2;
    const int wn   = wid & 3;
    const int bm   = blockIdx.y * 128;
    const int bn   = blockIdx.x * 128;

    float acc[4][4][4];
    #pragma unroll
    for (int i = 0; i < 4; i++)
        #pragma unroll
        for (int j = 0; j < 4; j++)
            #pragma unroll
            for (int q = 0; q < 4; q++) acc[i][j][q] = 0.f;

    const int a_row = wm * 64 + (lane & 15);
    const int a_cb  = (lane >> 4) * 16;
    const int b_row = wn * 32 + (lane & 7);
    const int b_cb  = ((lane >> 3) & 1) * 16;

    const int NC = K >> 6;
    load_chunk2(sbase,           A, B, bm, bn,  0, K, tid); CP_COMMIT();
    load_chunk2(sbase + STAGE_B, A, B, bm, bn, 64, K, tid); CP_COMMIT();

    int cs = 0, ps = 2;
    for (int c = 0; c < NC; c++) {
        CP_WAIT(1);
        __syncthreads();

        const uint32_t st = sbase + cs * STAGE_B;
        const uint32_t aA = st + a_row * TSTRIDE + a_cb;
        const uint32_t aB = st + TILE_B + b_row * TSTRIDE + b_cb;

        #pragma unroll
        for (int ks = 0; ks < 4; ks++) {
            uint32_t af[4][4], bf[4][2];
            #pragma unroll
            for (int mt = 0; mt < 4; mt++)
                ldmA(af[mt], aA + mt * (16 * TSTRIDE) + ks * 32);
            #pragma unroll
            for (int nt = 0; nt < 4; nt++)
                ldmB(bf[nt], aB + nt * (8 * TSTRIDE) + ks * 32);
            #pragma unroll
            for (int mt = 0; mt < 4; mt++)
                #pragma unroll
                for (int nt = 0; nt < 4; nt++)
                    mmaF16(acc[mt][nt], af[mt], bf[nt]);
        }

        if (c + 2 < NC)
            load_chunk2(sbase + ps * STAGE_B, A, B, bm, bn, (c + 2) << 6,
                        K, tid);
        CP_COMMIT();
        cs = (cs == 2) ? 0 : cs + 1;
        ps = (ps == 2) ? 0 : ps + 1;
    }

    // epilogue
    const float* bp = bias;
    int bofs = 0;
    if (EPI == 3) {
        bp   = (bn < 1024) ? bias : (bn < 2048) ? bias2 : bias3;
        bofs = bn & ~1023;
    }
    const int r0 = bm + wm * 64 + (lane >> 2);
    const int c0 = bn + wn * 32 + 2 * (lane & 3);
    #pragma unroll
    for (int mt = 0; mt < 4; mt++) {
        #pragma unroll
        for (int nt = 0; nt < 4; nt++) {
            const int col = c0 + nt * 8;
            const float2 bb = *(const float2*)(bp + col - bofs);
            #pragma unroll
            for (int half = 0; half < 2; half++) {
                const int row = r0 + mt * 16 + half * 8;
                const size_t off = (size_t)row * N + col;
                float v0 = acc[mt][nt][half * 2 + 0] + bb.x;
                float v1 = acc[mt][nt][half * 2 + 1] + bb.y;
                if (EPI == 1) {
                    const float2 rr = *(const float2*)(res + off);
                    v0 += rr.x; v1 += rr.y;
                }
                if (EPI == 2) {
                    v0 = gelu_exact(v0); v1 = gelu_exact(v1);
                    *(uint32_t*)(outH + off) = pack_f16(v0, v1);
                } else if (EPI == 3) {
                    *(uint32_t*)(outH + off) = pack_f16(v0, v1);
                } else {
                    float2 o; o.x = v0; o.y = v1;
                    *(float2*)(outF + off) = o;
                }
            }
        }
    }
}

// ---------------------------------------------------------------------------
// fp16 mma flash attention [verified R8]. Grid (SEQ/128, B*H), 256 thr.
// Q/K/V read from packed qkv [row][3072] (Q:+0, K:+1024, V:+2048).
// ---------------------------------------------------------------------------
#define AK_OFF    18432
#define AV_OFF    36864
#define AKV_STAGE 9216
#define ASMEM     55296

__device__ __forceinline__ void attn_load_kv(
    uint32_t sb, const __half* __restrict__ qkv, int rowKV, int hoff,
    int stage, int kt, int tid)
{
    const int rb = rowKV + kt * 64;
    #pragma unroll
    for (int i = 0; i < 4; i++) {
        const int idx  = i * 256 + tid;
        const int half = idx >> 9;
        const int r    = (idx >> 3) & 63;
        const int seg  = idx & 7;
        const int coff = (half ? 2048 : 1024) + hoff;
        const uint32_t dst = sb + (half ? AV_OFF : AK_OFF) +
                             stage * AKV_STAGE + r * 144 + seg * 16;
        cpasync16(dst, qkv + (size_t)(rb + r) * QKV_ST + coff + seg * 8);
    }
}

__global__ __launch_bounds__(256, 2) void attn_mma(
    const __half* __restrict__ qkv, __half* __restrict__ Oh)
{
    extern __shared__ char smem[];
    const uint32_t sb = smem_u32(smem);
    const int tid = threadIdx.x, lane = tid & 31, wid = tid >> 5;
    const int qt   = blockIdx.x;
    const int b    = blockIdx.y >> 4, h = blockIdx.y & 15;
    const int rowQ  = b * SEQLEN + qt * 128;
    const int rowKV = b * SEQLEN;
    const int hoff  = h * HDIM;

    #pragma unroll
    for (int i = 0; i < 4; i++) {
        const int idx = i * 256 + tid;
        const int r = idx >> 3, seg = idx & 7;
        cpasync16(sb + r * 144 + seg * 16,
                  qkv + (size_t)(rowQ + r) * QKV_ST + hoff + seg * 8);
    }
    attn_load_kv(sb, qkv, rowKV, hoff, 0, 0, tid);
    CP_COMMIT();
    attn_load_kv(sb, qkv, rowKV, hoff, 1, 1, tid);
    CP_COMMIT();

    CP_WAIT(1);
    __syncthreads();

    uint32_t qf[4][4];
    {
        const uint32_t qa = sb + (wid * 16 + (lane & 15)) * 144 +
                            (lane >> 4) * 16;
        #pragma unroll
        for (int ks = 0; ks < 4; ks++) ldmA(qf[ks], qa + ks * 32);
    }

    float o[8][4];
    #pragma unroll
    for (int nt = 0; nt < 8; nt++)
        #pragma unroll
        for (int j = 0; j < 4; j++) o[nt][j] = 0.f;
    float mrun[2] = {-1e30f, -1e30f}, lrun[2] = {0.f, 0.f};

    const uint32_t koff_l = (lane & 7) * 144 + ((lane >> 3) & 1) * 16;
    const uint32_t voff_l = (lane & 15) * 144;
    constexpr int NKT = SEQLEN / 64;

    for (int kt = 0; kt < NKT; kt++) {
        if (kt > 0) {
            if (kt + 1 < NKT) { CP_WAIT(1); } else { CP_WAIT(0); }
            __syncthreads();
        }
        const int stage = kt & 1;
        const uint32_t skb = sb + AK_OFF + stage * AKV_STAGE;
        const uint32_t svb = sb + AV_OFF + stage * AKV_STAGE;

        float sacc[8][4];
        #pragma unroll
        for (int nt = 0; nt < 8; nt++)
            #pragma unroll
            for (int j = 0; j < 4; j++) sacc[nt][j] = 0.f;
        #pragma unroll
        for (int ks = 0; ks < 4; ks++) {
            #pragma unroll
            for (int nt = 0; nt < 8; nt++) {
                uint32_t kf[2];
                ldmB(kf, skb + nt * (8 * 144) + koff_l + ks * 32);
                mmaF16(sacc[nt], qf[ks], kf);
            }
        }

        float corr[2];
        #pragma unroll
        for (int hf = 0; hf < 2; hf++) {
            const int i0 = hf * 2, i1 = hf * 2 + 1;
            float mx = fmaxf(sacc[0][i0], sacc[0][i1]);
            #pragma unroll
            for (int nt = 1; nt < 8; nt++)
                mx = fmaxf(mx, fmaxf(sacc[nt][i0], sacc[nt][i1]));
            mx = fmaxf(mx, __shfl_xor_sync(0xffffffffu, mx, 1));
            mx = fmaxf(mx, __shfl_xor_sync(0xffffffffu, mx, 2));
            const float mn = fmaxf(mrun[hf], mx);
            const float cm = C_SCALE * mn;
            corr[hf] = exp2_fast(fmaf(C_SCALE, mrun[hf], -cm));
            float sum = 0.f;
            #pragma unroll
            for (int nt = 0; nt < 8; nt++) {
                const float p0 = exp2_fast(fmaf(sacc[nt][i0], C_SCALE, -cm));
                const float p1 = exp2_fast(fmaf(sacc[nt][i1], C_SCALE, -cm));
                sacc[nt][i0] = p0; sacc[nt][i1] = p1;
                sum += p0 + p1;
            }
            sum += __shfl_xor_sync(0xffffffffu, sum, 1);
            sum += __shfl_xor_sync(0xffffffffu, sum, 2);
            lrun[hf] = lrun[hf] * corr[hf] + sum;
            mrun[hf] = mn;
        }

        uint32_t pa[4][4];
        #pragma unroll
        for (int t = 0; t < 4; t++) {
            pa[t][0] = pack_f16(sacc[2 * t][0],     sacc[2 * t][1]);
            pa[t][1] = pack_f16(sacc[2 * t][2],     sacc[2 * t][3]);
            pa[t][2] = pack_f16(sacc[2 * t + 1][0], sacc[2 * t + 1][1]);
            pa[t][3] = pack_f16(sacc[2 * t + 1][2], sacc[2 * t + 1][3]);
        }

        #pragma unroll
        for (int nt = 0; nt < 8; nt++) {
            o[nt][0] *= corr[0]; o[nt][1] *= corr[0];
            o[nt][2] *= corr[1]; o[nt][3] *= corr[1];
        }
        #pragma unroll
        for (int t = 0; t < 4; t++) {
            #pragma unroll
            for (int nt = 0; nt < 8; nt++) {
                uint32_t vf[2];
                ldmBT(vf, svb + t * (16 * 144) + voff_l + nt * 16);
                mmaF16(o[nt], pa[t], vf);
            }
        }

        __syncthreads();
        if (kt + 2 < NKT) {
            attn_load_kv(sb, qkv, rowKV, hoff, stage, kt + 2, tid);
            CP_COMMIT();
        }
    }

    const float inv0 = 1.0f / lrun[0], inv1 = 1.0f / lrun[1];
    const int rg = rowQ + wid * 16 + (lane >> 2);
    const int cg = hoff + 2 * (lane & 3);
    #pragma unroll
    for (int nt = 0; nt < 8; nt++) {
        #pragma unroll
        for (int hf = 0; hf < 2; hf++) {
            const float inv = hf ? inv1 : inv0;
            const size_t off = (size_t)(rg + hf * 8) * CDIM + cg + nt * 8;
            *(uint32_t*)(Oh + off) =
                pack_f16(o[nt][hf * 2 + 0] * inv, o[nt][hf * 2 + 1] * inv);
        }
    }
}

// ---------------------------------------------------------------------------
// kernel_launch — weight prep forked onto a side stream (captured fork/join)
// ---------------------------------------------------------------------------
extern "C" void kernel_launch(void* const* d_in, const int* in_sizes, int n_in,
                              void* d_out, int out_size)
{
    const float* x   = (const float*)d_in[0];
    const float* g1  = (const float*)d_in[1];
    const float* b1  = (const float*)d_in[2];
    const float* Wq  = (const float*)d_in[3];
    const float* bq  = (const float*)d_in[4];
    const float* Wk  = (const float*)d_in[5];
    const float* bk  = (const float*)d_in[6];
    const float* Wv  = (const float*)d_in[7];
    const float* bv  = (const float*)d_in[8];
    const float* Wo  = (const float*)d_in[9];
    const float* bo  = (const float*)d_in[10];
    const float* g2  = (const float*)d_in[11];
    const float* b2  = (const float*)d_in[12];
    const float* W1  = (const float*)d_in[13];
    const float* bf1 = (const float*)d_in[14];
    const float* W2  = (const float*)d_in[15];
    const float* bf2 = (const float*)d_in[16];
    float* out = (float*)d_out;

    float *px1;
    __half *ph, *pqkv, *po, *pf, *pwqkv, *pwo, *pw1t, *pw2t;
    cudaGetSymbolAddress((void**)&px1,   g_x1);
    cudaGetSymbolAddress((void**)&ph,    g_h);
    cudaGetSymbolAddress((void**)&pqkv,  g_qkv);
    cudaGetSymbolAddress((void**)&po,    g_o);
    cudaGetSymbolAddress((void**)&pf,    g_f);
    cudaGetSymbolAddress((void**)&pwqkv, g_wqkv);
    cudaGetSymbolAddress((void**)&pwo,   g_wo);
    cudaGetSymbolAddress((void**)&pw1t,  g_w1t);
    cudaGetSymbolAddress((void**)&pw2t,  g_w2t);

    cudaFuncSetAttribute(mma_gemm<1>, cudaFuncAttributeMaxDynamicSharedMemorySize, GSMEM);
    cudaFuncSetAttribute(mma_gemm<2>, cudaFuncAttributeMaxDynamicSharedMemorySize, GSMEM);
    cudaFuncSetAttribute(mma_gemm<3>, cudaFuncAttributeMaxDynamicSharedMemorySize, GSMEM);
    cudaFuncSetAttribute(attn_mma,    cudaFuncAttributeMaxDynamicSharedMemorySize, ASMEM);

    // Side stream + events: created once on the (uncaptured) correctness
    // call; replayed as fork/join nodes inside the captured graph.
    static cudaStream_t s1 = nullptr;
    static cudaEvent_t evF = nullptr, evA = nullptr, evB = nullptr;
    if (!s1) {
        cudaStreamCreateWithFlags(&s1, cudaStreamNonBlocking);
        cudaEventCreateWithFlags(&evF, cudaEventDisableTiming);
        cudaEventCreateWithFlags(&evA, cudaEventDisableTiming);
        cudaEventCreateWithFlags(&evB, cudaEventDisableTiming);
    }

    const dim3 gQKV(QKV_ST / 128, MTOT / 128);   // (24, 32)
    const dim3 gP  (CDIM / 128,   MTOT / 128);   // (8, 32)
    const dim3 gF1 (HIDDIM / 128, MTOT / 128);   // (32, 32)

    // ---- fork: weight prep on s1 ----
    cudaEventRecord(evF, 0);
    cudaStreamWaitEvent(s1, evF, 0);
    wtrans4_kernel<<<dim3(32, 32, 4), 256, 0, s1>>>(Wq, Wk, Wv, Wo, pwqkv, pwo);
    cudaEventRecord(evA, s1);                        // QKV/Wo weights ready
    wtrans_kernel<<<dim3(HIDDIM / 32, CDIM / 32), 256, 0, s1>>>(
        W1, pw1t, CDIM, HIDDIM);
    wtrans_kernel<<<dim3(CDIM / 32, HIDDIM / 32), 256, 0, s1>>>(
        W2, pw2t, HIDDIM, CDIM);
    cudaEventRecord(evB, s1);                        // FFN weights ready

    // ---- main chain ----
    ln_kernel<<<MTOT / 8, 256>>>(x, g1, b1, ph);                  // LN1
    cudaStreamWaitEvent(0, evA, 0);
    mma_gemm<3><<<gQKV, 256, GSMEM>>>(ph, pwqkv, bq, bk, bv, nullptr,
                                      nullptr, pqkv, CDIM, QKV_ST);
    attn_mma<<<dim3(SEQLEN / 128, NBATCH * NHEADS), 256, ASMEM>>>(pqkv, po);
    mma_gemm<1><<<gP, 256, GSMEM>>>(po, pwo, bo, nullptr, nullptr, x,
                                    px1, nullptr, CDIM, CDIM);    // Wo + res
    ln_kernel<<<MTOT / 8, 256>>>(px1, g2, b2, ph);                // LN2
    cudaStreamWaitEvent(0, evB, 0);
    mma_gemm<2><<<gF1, 256, GSMEM>>>(ph, pw1t, bf1, nullptr, nullptr, nullptr,
                                     nullptr, pf, CDIM, HIDDIM);  // FFN1+GELU
    mma_gemm<1><<<gP, 256, GSMEM>>>(pf, pw2t, bf2, nullptr, nullptr, px1,
                                    out, nullptr, HIDDIM, CDIM);  // FFN2 + res
}